// round 5
// baseline (speedup 1.0000x reference)
#include <cuda_runtime.h>
#include <cstdint>

typedef unsigned long long u64;
typedef unsigned u32;

#define N13   16224           // 32*3*169   (multiple of 32)
#define N26   64896           // 32*3*676
#define N52   259584          // 32*3*2704
#define NT    340704
#define CAP   4096
#define NK    512
#define NSEL  1024            // selection superset target
#define GRID  148
#define BLK   1024
#define NTH   (GRID*BLK)

// ---------------- scratch (static device globals: no allocation) ------------
__device__ u64   g_valid[NT];         // (o0 bits << 32) | linear index t
__device__ u64   g_keys[NT];          // approx keys, compact [0, vcnt)
__device__ u32   g_hist1[2048];
__device__ u32   g_hist2[2048];
__device__ u32   g_cnt;
__device__ u32   g_vcnt;
__device__ u32   g_bwork;
__device__ u64   g_gbuf[CAP];
__device__ u32   g_bar_arrive;
__device__ u32   g_bar_gen;

__device__ __forceinline__ u32 fordf(float f) {
    u32 u = __float_as_uint(f);
    return (u & 0x80000000u) ? ~u : (u | 0x80000000u);
}
__device__ __forceinline__ float ifordf(u32 e) {
    return __uint_as_float((e & 0x80000000u) ? (e & 0x7fffffffu) : ~e);
}

// grid barrier: exactly one block per SM (GRID=148, launch_bounds(1024,1))
__device__ __forceinline__ void grid_barrier() {
    __syncthreads();
    __threadfence();
    if (threadIdx.x == 0) {
        volatile u32* vgen = &g_bar_gen;
        u32 gen = *vgen;
        __threadfence();
        u32 a = atomicAdd(&g_bar_arrive, 1u);
        if (a == GRID - 1u) {
            g_bar_arrive = 0u;
            __threadfence();
            atomicAdd(&g_bar_gen, 1u);
        } else {
            while (*vgen == gen) {}
        }
    }
    __threadfence();
    __syncthreads();
}

// ---------------- approx scorer (valid cells only, __expf) ------------------
template <int S, int GOFF>
__device__ __forceinline__ void approx_item(u32 t, u32 o0b, u32 slot,
                                            const float* __restrict__ src,
                                            u32* shist) {
    const int SS = S * S;
    int plane = t / SS, cell = t - plane * SS;
    int b = plane / 3, a = plane - 3 * b;
    const float* cp = src + (size_t)(b * 255 + a * 85 + 5) * SS + cell;
    float m = -1e30f, sum = 0.f;
#pragma unroll 16
    for (int c = 0; c < 80; ++c) {
        float l = __ldcs(cp + (size_t)c * SS);
        sum += __expf(l);
        m = fmaxf(m, l);
    }
    float o0 = __uint_as_float(o0b);
    float obj = 1.f / (1.f + __expf(-o0));
    float p = obj * __expf(m) / sum;
    u32 id = (u32)GOFF + (u32)((b * SS + cell) * 3 + a);
    u32 fs = fordf(p);
    g_keys[slot] = ((u64)fs << 32) | (u32)(~id);
    atomicAdd(&shist[fs >> 21], 1u);
}

// suffix scan of a 2048-bin histogram; find threshold bucket
__device__ __forceinline__ void suffix_select(u32* sa, u32* sb, const u32* ghist,
                                              u32 target, int* out_b, u32* out_above) {
    int tid = threadIdx.x;
    for (int i = tid; i < 2048; i += BLK) sa[i] = ghist[i];
    __syncthreads();
    u32 *src = sa, *dst = sb;
    for (int off = 1; off < 2048; off <<= 1) {
        for (int i = tid; i < 2048; i += BLK) {
            u32 v = src[i];
            if (i + off < 2048) v += src[i + off];
            dst[i] = v;
        }
        __syncthreads();
        u32* tmp = src; src = dst; dst = tmp;
    }
    for (int i = tid; i < 2048; i += BLK) {
        bool cross = (src[i] >= target) && (i == 2047 || src[i + 1] < target);
        if (cross) {
            *out_b = i;
            if (out_above) *out_above = (i == 2047) ? 0u : src[i + 1];
        }
    }
    __syncthreads();
}

// map candidate id -> (S, src, anc, b, a, cell)
__device__ __forceinline__ void map_id(u32 id,
    const float* o13, const float* o26, const float* o52,
    const float* a13, const float* a26, const float* a52,
    int& S, const float*& src, const float*& anc, int& a, int& b, int& cell) {
    u32 rid = id;
    if (id < N13)            { S = 13; src = o13; anc = a13; }
    else if (id < N13 + N26) { S = 26; src = o26; anc = a26; rid = id - N13; }
    else                     { S = 52; src = o52; anc = a52; rid = id - (N13 + N26); }
    a = rid % 3;
    u32 q = rid / 3;
    int SS = S * S;
    b = q / SS;
    cell = q - b * SS;
}

// ---------------- megakernel --------------------------------------------------
__global__ void __launch_bounds__(BLK, 1) k_mega(
    const float* __restrict__ o13, const float* __restrict__ o26,
    const float* __restrict__ o52,
    const float* __restrict__ a13, const float* __restrict__ a26,
    const float* __restrict__ a52,
    const float* __restrict__ c1p, const float* __restrict__ c2p,
    float* __restrict__ out, int out_size)
{
    __shared__ __align__(16) unsigned char sm[47104];
    __shared__ int   s_b1, s_b2;
    __shared__ u32   s_cA1;
    __shared__ u32   s_cnt, s_vcnt;
    __shared__ u32   s_a0w[16], s_keep[16];
    __shared__ int   s_aliveIdx[NK];
    __shared__ int   s_kOf[NK];
    __shared__ int   s_nA;
    __shared__ float s_red[32];
    __shared__ float s_maxp;

    const int tid = threadIdx.x;
    const int gt = blockIdx.x * BLK + tid;
    const int lane = tid & 31;

    if (gt == NTH - 1) g_cnt = 0;           // 3 barriers before first use
    if (tid == 0) { s_b1 = -1; s_b2 = 0; s_cA1 = 0; }
    u32* shist = (u32*)sm;
    for (int i = tid; i < 2048; i += BLK) shist[i] = 0;
    __syncthreads();

    // ===== Phase A: read obj channel only; compact valid cell ids =====
    for (int t = gt; t < NT; t += NTH) {    // N13, N13+N26 are multiples of 32 -> warp-uniform branches
        float o0;
        if (t < N13) {
            const int SS = 169;
            int plane = t / SS, cell = t - plane * SS;
            int b = plane / 3, a = plane - 3 * b;
            o0 = __ldg(o13 + (size_t)(b * 255 + a * 85) * SS + cell);
        } else if (t < N13 + N26) {
            int tt = t - N13;
            const int SS = 676;
            int plane = tt / SS, cell = tt - plane * SS;
            int b = plane / 3, a = plane - 3 * b;
            o0 = __ldg(o26 + (size_t)(b * 255 + a * 85) * SS + cell);
        } else {
            int tt = t - (N13 + N26);
            const int SS = 2704;
            int plane = tt / SS, cell = tt - plane * SS;
            int b = plane / 3, a = plane - 3 * b;
            o0 = __ldg(o52 + (size_t)(b * 255 + a * 85) * SS + cell);
        }
        bool val = o0 > 0.f;
        u32 msk = __ballot_sync(0xffffffffu, val);
        u32 nv = __popc(msk);
        u32 basep = 0;
        if (lane == 0 && nv) basep = atomicAdd(&g_vcnt, nv);
        basep = __shfl_sync(0xffffffffu, basep, 0);
        if (val) {
            u32 pos = basep + __popc(msk & ((1u << lane) - 1u));
            g_valid[pos] = ((u64)__float_as_uint(o0) << 32) | (u32)t;
        }
    }
    grid_barrier();

    // ===== Phase B: approx score valid cells via work-stealing =====
    if (tid == 0) s_vcnt = g_vcnt;
    __syncthreads();
    const u32 vc = s_vcnt;
    for (;;) {
        u32 basep = 0;
        if (lane == 0) basep = atomicAdd(&g_bwork, 32u);
        basep = __shfl_sync(0xffffffffu, basep, 0);
        if (basep >= vc) break;
        u32 u_ = basep + (u32)lane;
        if (u_ < vc) {
            u64 it = g_valid[u_];
            u32 t = (u32)it;
            u32 o0b = (u32)(it >> 32);
            if (t < N13)            approx_item<13, 0>(t, o0b, u_, o13, shist);
            else if (t < N13 + N26) approx_item<26, N13>(t - N13, o0b, u_, o26, shist);
            else                    approx_item<52, N13 + N26>(t - (N13 + N26), o0b, u_, o52, shist);
        }
    }
    __syncthreads();
    for (int i = tid; i < 2048; i += BLK) {
        u32 v = shist[i];
        if (v) atomicAdd(&g_hist1[i], v);
    }
    grid_barrier();

    // ===== P2+P3: select b1 (target NSEL), build hist2 =====
    {
        u32* sa = (u32*)sm; u32* sb = sa + 2048;
        suffix_select(sa, sb, g_hist1, (u32)NSEL, &s_b1, &s_cA1);
        u32* sh2 = (u32*)sm;
        for (int i = tid; i < 2048; i += BLK) sh2[i] = 0;
        __syncthreads();
        int B1 = s_b1;
        for (u32 t = (u32)gt; t < vc; t += NTH) {
            u64 k = g_keys[t];
            if ((int)(u32)(k >> 53) == B1)
                atomicAdd(&sh2[(u32)(k >> 42) & 2047u], 1u);
        }
        __syncthreads();
        for (int i = tid; i < 2048; i += BLK) {
            u32 v = sh2[i];
            if (v) atomicAdd(&g_hist2[i], v);
        }
    }
    grid_barrier();

    // ===== P4+P5: select b2, gather superset =====
    {
        u32* sa = (u32*)sm; u32* sb = sa + 2048;
        suffix_select(sa, sb, g_hist2, (u32)NSEL - s_cA1, &s_b2, 0);
        int B1 = s_b1, B2 = s_b2;   // if B1==-1 (degenerate): gather all
        for (u32 t = (u32)gt; t < vc; t += NTH) {
            u64 k = g_keys[t];
            int b1 = (int)(u32)(k >> 53);
            int b2 = (int)((u32)(k >> 42) & 2047u);
            if (b1 > B1 || (b1 == B1 && b2 >= B2)) {
                u32 pos = atomicAdd(&g_cnt, 1u);
                if (pos < (u32)CAP) g_gbuf[pos] = k;
            }
        }
    }
    grid_barrier();   // last barrier

    // tail-fill of out beyond 512*7
    for (int i = NK * 7 + gt; i < out_size; i += NTH) out[i] = 0.f;

    if (blockIdx.x == 1) {          // scratch reset for next replay (nothing reads these now)
        for (int i = tid; i < 2048; i += BLK) { g_hist1[i] = 0; g_hist2[i] = 0; }
        if (tid == 0) { g_bwork = 0; g_vcnt = 0; }
    }
    if (blockIdx.x != 0) return;

    // =================== block 0: exact rescore + rank + NMS + output ==========
    u64*   skeys = (u64*)sm;                              // [0, 32768)
    float* scand = (float*)(sm + 32768);                  // [32768, 45056)
    unsigned char* salive = (unsigned char*)(sm + 45056); // 512 B

    if (tid == 0) { s_cnt = g_cnt; s_nA = 0; }
    __syncthreads();
    u32 cnt = s_cnt; if (cnt > (u32)CAP) cnt = CAP;
    for (int i = tid; i < NK * 6; i += BLK) scand[i] = 0.f;
    if (tid < NK) salive[tid] = 0;
    float c1 = *c1p, c2 = *c2p;

    // pass 1: exact scores (bit-identical formula to the R4-passing kernel)
    for (u32 j = tid; j < cnt; j += BLK) {
        u32 id = ~(u32)g_gbuf[j];
        int S, a, b, cell;
        const float *src, *anc;
        map_id(id, o13, o26, o52, a13, a26, a52, S, src, anc, a, b, cell);
        int SS = S * S;
        const float* pc = src + (size_t)(b * 255 + a * 85) * SS + cell;
        float m = -1e30f, sum = 0.f; int am = 0;
#pragma unroll 8
        for (int c = 0; c < 80; ++c) {
            float l = pc[(size_t)(5 + c) * SS];
            sum += expf(l);
            if (l > m) { m = l; am = c; }
        }
        float o0 = pc[0];
        float obj = 1.f / (1.f + expf(-o0));
        float p = obj * expf(m) / sum;
        skeys[j] = ((u64)fordf(p) << 32) | (u32)(~((id << 7) | (u32)am));
    }
    __syncthreads();

    // pass 2: exact ranks + box computation for ranks < 512
    for (u32 j = tid; j < cnt; j += BLK) {
        u64 kj = skeys[j];
        int r = 0; u32 i = 0;
        for (; i + 4 <= cnt; i += 4)
            r += (int)(skeys[i] > kj) + (int)(skeys[i+1] > kj)
               + (int)(skeys[i+2] > kj) + (int)(skeys[i+3] > kj);
        for (; i < cnt; ++i) r += (int)(skeys[i] > kj);
        if (r < NK && (u32)(kj >> 32) > 0x80000000u) {
            u32 v = ~(u32)kj;
            u32 id = v >> 7;
            int cls = (int)(v & 127u);
            int S, a, b, cell;
            const float *src, *anc;
            map_id(id, o13, o26, o52, a13, a26, a52, S, src, anc, a, b, cell);
            int SS = S * S;
            const float* pc = src + (size_t)(b * 255 + a * 85) * SS + cell;
            float o1 = pc[(size_t)SS],     o2 = pc[(size_t)2 * SS];
            float o3 = pc[(size_t)3 * SS], o4 = pc[(size_t)4 * SS];
            int y = cell / S, x = cell - y * S;
            float sc = 416.f / (float)S;
            float cx = ((float)x + o1) * sc / c1;
            float cy = ((float)y + o2) * sc / c2;
            float w  = expf(o3) * anc[2 * a] / c1;
            float h  = expf(o4) * anc[2 * a + 1] / c2;
            float p  = ifordf((u32)(kj >> 32));
            float* cd = scand + r * 6;
            cd[0] = p; cd[1] = cx; cd[2] = cy; cd[3] = w; cd[4] = h; cd[5] = (float)cls;
            salive[r] = 1;
        }
    }
    __syncthreads();

    // maxp over alive candidates
    {
        float p = 0.f;
        if (tid < NK && salive[tid]) p = scand[tid * 6];
        for (int o = 16; o > 0; o >>= 1) p = fmaxf(p, __shfl_xor_sync(0xffffffffu, p, o));
        if (lane == 0) s_red[tid >> 5] = p;
        __syncthreads();
        if (tid < 32) {
            float v = s_red[tid];
            for (int o = 16; o > 0; o >>= 1) v = fmaxf(v, __shfl_xor_sync(0xffffffffu, v, o));
            if (tid == 0) s_maxp = v;
        }
        __syncthreads();
    }

    // alive0 mask + compaction of alive rows
    if (tid < NK) {
        bool a0 = salive[tid] && (scand[tid * 6] > 0.5f * s_maxp);
        u32 m = __ballot_sync(0xffffffffu, a0);
        if (lane == 0) s_a0w[tid >> 5] = m;
        if (a0) {
            int k = atomicAdd(&s_nA, 1);
            s_aliveIdx[k] = tid;
            s_kOf[tid] = k;
        }
    }
    __syncthreads();

    // IoU suppress rows ONLY for alive0 candidates (reuse skeys region)
    u32* ssup = (u32*)sm;                     // nA*16 u32 <= 32 KB
    {
        int nA = s_nA;
        int w = tid >> 5;
        for (int k = w; k < nA; k += 32) {
            int i = s_aliveIdx[k];
            float cxi = scand[i*6+1], cyi = scand[i*6+2];
            float wi  = scand[i*6+3], hi  = scand[i*6+4], cli = scand[i*6+5];
            float x1i = cxi - wi * 0.5f, y1i = cyi - hi * 0.5f;
            float x2i = x1i + wi,        y2i = y1i + hi;
            float ai = (x2i - x1i) * (y2i - y1i);
            for (int cw = 0; cw < 16; ++cw) {
                int j = (cw << 5) + lane;
                const float* bj = scand + j * 6;
                float wj = bj[3], hj = bj[4];
                float x1j = bj[1] - wj * 0.5f, y1j = bj[2] - hj * 0.5f;
                float x2j = x1j + wj,          y2j = y1j + hj;
                float iw = fmaxf(fminf(x2i, x2j) - fmaxf(x1i, x1j), 0.f);
                float ih = fmaxf(fminf(y2i, y2j) - fmaxf(y1i, y1j), 0.f);
                float inter = iw * ih;
                float aj = (x2j - x1j) * (y2j - y1j);
                float iou = inter / (ai + aj - inter);
                bool sup = (cli == bj[5]) || (iou >= 0.5f);
                u32 msk = __ballot_sync(0xffffffffu, sup);
                if (lane == 0) ssup[k * 16 + cw] = msk;
            }
        }
    }
    __syncthreads();

    // serial cascade with ffs-skip (single thread; work ~ #keeps)
    if (tid == 0) {
        u32 sup[16], keep[16];
#pragma unroll
        for (int x = 0; x < 16; ++x) { sup[x] = ~s_a0w[x]; keep[x] = 0u; }
        for (int w = 0; w < 16; ++w) {
            u32 avail = ~sup[w];
            while (avail) {
                int bb = __ffs(avail) - 1;
                int i = (w << 5) + bb;
                keep[w] |= (1u << bb);
                int k = s_kOf[i];
#pragma unroll
                for (int x = 0; x < 16; ++x) sup[x] |= ssup[k * 16 + x];
                u32 hi = (bb == 31) ? 0u : (0xffffffffu << (bb + 1));
                avail = ~sup[w] & hi;
            }
        }
#pragma unroll
        for (int x = 0; x < 16; ++x) s_keep[x] = keep[x];
    }
    __syncthreads();

    // output
    if (tid < NK) {
        bool kp = (s_keep[tid >> 5] >> (tid & 31)) & 1u;
        float km = kp ? 1.f : 0.f;
        if (out_size >= NK * 6) {
#pragma unroll
            for (int c = 0; c < 6; ++c) out[tid * 6 + c] = scand[tid * 6 + c] * km;
        }
        if (out_size >= NK * 7) out[NK * 6 + tid] = km;
    }
}

// ---------------- launch: ONE kernel ------------------------------------------
extern "C" void kernel_launch(void* const* d_in, const int* in_sizes, int n_in,
                              void* d_out, int out_size) {
    k_mega<<<GRID, BLK>>>(
        (const float*)d_in[0], (const float*)d_in[1], (const float*)d_in[2],
        (const float*)d_in[3], (const float*)d_in[4], (const float*)d_in[5],
        (const float*)d_in[6], (const float*)d_in[7],
        (float*)d_out, out_size);
}

// round 6
// speedup vs baseline: 1.0509x; 1.0509x over previous
#include <cuda_runtime.h>
#include <cstdint>

typedef unsigned long long u64;
typedef unsigned u32;

#define N13   16224           // 32*3*169   (multiple of 32)
#define N26   64896           // 32*3*676
#define N52   259584          // 32*3*2704
#define NT    340704
#define CAP   4096
#define NK    512
#define NSEL  1024            // selection superset target
#define GRID  148
#define BLK   1024
#define NTH   (GRID*BLK)

// ---------------- scratch (static device globals: no allocation) ------------
__device__ u64   g_keys[NT];
__device__ u32   g_hist1[2048];
__device__ u32   g_hist2[2048];
__device__ u32   g_cnt;
__device__ u32   g_work;
__device__ u64   g_gbuf[CAP];
__device__ u32   g_bar_arrive;
__device__ u32   g_bar_gen;

__device__ __forceinline__ u32 fordf(float f) {
    u32 u = __float_as_uint(f);
    return (u & 0x80000000u) ? ~u : (u | 0x80000000u);
}
__device__ __forceinline__ float ifordf(u32 e) {
    return __uint_as_float((e & 0x80000000u) ? (e & 0x7fffffffu) : ~e);
}

// grid barrier: exactly one block per SM (GRID=148, launch_bounds(1024,1))
__device__ __forceinline__ void grid_barrier() {
    __syncthreads();
    __threadfence();
    if (threadIdx.x == 0) {
        volatile u32* vgen = &g_bar_gen;
        u32 gen = *vgen;
        __threadfence();
        u32 a = atomicAdd(&g_bar_arrive, 1u);
        if (a == GRID - 1u) {
            g_bar_arrive = 0u;
            __threadfence();
            atomicAdd(&g_bar_gen, 1u);
        } else {
            while (*vgen == gen) {}
        }
    }
    __threadfence();
    __syncthreads();
}

// ---------------- approx per-cell scorer (ALL cells, coalesced, __expf) -----
template <int S, int GOFF>
__device__ __forceinline__ void approx_cell(u32 rel, u32 slot,
                                            const float* __restrict__ src,
                                            u32* shist) {
    const int SS = S * S;
    int plane = rel / SS;
    int cell  = rel - plane * SS;
    int b = plane / 3, a = plane - 3 * b;
    const float* pc = src + (size_t)(b * 255 + a * 85) * SS + cell;
    float o0 = __ldcs(pc);
    float m = -1e30f, sum = 0.f;
    const float* cp = pc + (size_t)5 * SS;
#pragma unroll 8
    for (int c = 0; c < 80; ++c) {
        float l = __ldcs(cp);
        cp += SS;
        sum += __expf(l);
        m = fmaxf(m, l);
    }
    float score = -1.f;
    if (o0 > 0.f) {
        float obj = 1.f / (1.f + __expf(-o0));
        score = obj * __expf(m) / sum;
    }
    u32 id = (u32)GOFF + (u32)((b * SS + cell) * 3 + a);
    u32 fs = fordf(score);
    g_keys[slot] = ((u64)fs << 32) | (u32)(~id);
    atomicAdd(&shist[fs >> 21], 1u);
}

// suffix scan of a 2048-bin histogram; find threshold bucket
__device__ __forceinline__ void suffix_select(u32* sa, u32* sb, const u32* ghist,
                                              u32 target, int* out_b, u32* out_above) {
    int tid = threadIdx.x;
    for (int i = tid; i < 2048; i += BLK) sa[i] = ghist[i];
    __syncthreads();
    u32 *src = sa, *dst = sb;
    for (int off = 1; off < 2048; off <<= 1) {
        for (int i = tid; i < 2048; i += BLK) {
            u32 v = src[i];
            if (i + off < 2048) v += src[i + off];
            dst[i] = v;
        }
        __syncthreads();
        u32* tmp = src; src = dst; dst = tmp;
    }
    for (int i = tid; i < 2048; i += BLK) {
        bool cross = (src[i] >= target) && (i == 2047 || src[i + 1] < target);
        if (cross) {
            *out_b = i;
            if (out_above) *out_above = (i == 2047) ? 0u : src[i + 1];
        }
    }
    __syncthreads();
}

// map candidate id -> (S, src, anc, b, a, cell)
__device__ __forceinline__ void map_id(u32 id,
    const float* o13, const float* o26, const float* o52,
    const float* a13, const float* a26, const float* a52,
    int& S, const float*& src, const float*& anc, int& a, int& b, int& cell) {
    u32 rid = id;
    if (id < N13)            { S = 13; src = o13; anc = a13; }
    else if (id < N13 + N26) { S = 26; src = o26; anc = a26; rid = id - N13; }
    else                     { S = 52; src = o52; anc = a52; rid = id - (N13 + N26); }
    a = rid % 3;
    u32 q = rid / 3;
    int SS = S * S;
    b = q / SS;
    cell = q - b * SS;
}

// ---------------- megakernel --------------------------------------------------
__global__ void __launch_bounds__(BLK, 1) k_mega(
    const float* __restrict__ o13, const float* __restrict__ o26,
    const float* __restrict__ o52,
    const float* __restrict__ a13, const float* __restrict__ a26,
    const float* __restrict__ a52,
    const float* __restrict__ c1p, const float* __restrict__ c2p,
    float* __restrict__ out, int out_size)
{
    __shared__ __align__(16) unsigned char sm[47104];
    __shared__ int   s_b1, s_b2;
    __shared__ u32   s_cA1;
    __shared__ u32   s_cnt;
    __shared__ u32   s_a0w[16], s_keep[16];
    __shared__ int   s_aliveIdx[NK];
    __shared__ int   s_kOf[NK];
    __shared__ int   s_nA;
    __shared__ float s_red[32];
    __shared__ float s_maxp;

    const int tid = threadIdx.x;
    const int gt = blockIdx.x * BLK + tid;
    const int lane = tid & 31;

    if (gt == NTH - 1) g_cnt = 0;           // 3 barriers before first use

    // ===== P1: approx-score ALL cells via warp work-stealing (coalesced) =====
    {
        u32* shist = (u32*)sm;
        for (int i = tid; i < 2048; i += BLK) shist[i] = 0;
        __syncthreads();
        for (;;) {
            u32 base = 0;
            if (lane == 0) base = atomicAdd(&g_work, 32u);
            base = __shfl_sync(0xffffffffu, base, 0);
            if (base >= (u32)NT) break;
            u32 u = base + (u32)lane;
            if (u < (u32)NT) {
                if (u < N13)             approx_cell<13, 0>(u, u, o13, shist);
                else if (u < N13 + N26)  approx_cell<26, N13>(u - N13, u, o26, shist);
                else                     approx_cell<52, N13 + N26>(u - (N13 + N26), u, o52, shist);
            }
        }
        __syncthreads();
        for (int i = tid; i < 2048; i += BLK) {
            u32 v = shist[i];
            if (v) atomicAdd(&g_hist1[i], v);
        }
    }
    grid_barrier();

    // ===== P2+P3: every block selects b1 (target NSEL), then builds hist2 =====
    {
        u32* sa = (u32*)sm; u32* sb = sa + 2048;
        suffix_select(sa, sb, g_hist1, (u32)NSEL, &s_b1, &s_cA1);
        u32* sh2 = (u32*)sm;
        for (int i = tid; i < 2048; i += BLK) sh2[i] = 0;
        __syncthreads();
        int B1 = s_b1;
        for (int t = gt; t < NT; t += NTH) {
            u64 k = g_keys[t];
            if ((int)(u32)(k >> 53) == B1)
                atomicAdd(&sh2[(u32)(k >> 42) & 2047u], 1u);
        }
        __syncthreads();
        for (int i = tid; i < 2048; i += BLK) {
            u32 v = sh2[i];
            if (v) atomicAdd(&g_hist2[i], v);
        }
    }
    grid_barrier();

    // ===== P4+P5: every block selects b2, then gathers superset =====
    {
        u32* sa = (u32*)sm; u32* sb = sa + 2048;
        suffix_select(sa, sb, g_hist2, (u32)NSEL - s_cA1, &s_b2, 0);
        int B1 = s_b1, B2 = s_b2;
        for (int t = gt; t < NT; t += NTH) {
            u64 k = g_keys[t];
            int b1 = (int)(u32)(k >> 53);
            int b2 = (int)((u32)(k >> 42) & 2047u);
            if (b1 > B1 || (b1 == B1 && b2 >= B2)) {
                u32 pos = atomicAdd(&g_cnt, 1u);
                if (pos < (u32)CAP) g_gbuf[pos] = k;
            }
        }
    }
    grid_barrier();   // last barrier

    // tail-fill of out beyond 512*7
    for (int i = NK * 7 + gt; i < out_size; i += NTH) out[i] = 0.f;

    if (blockIdx.x == 1) {          // scratch reset for next replay
        for (int i = tid; i < 2048; i += BLK) { g_hist1[i] = 0; g_hist2[i] = 0; }
        if (tid == 0) g_work = 0;
    }
    if (blockIdx.x != 0) return;

    // =================== block 0: exact rescore + rank + NMS + output ==========
    u64*   skeys = (u64*)sm;                              // [0, 32768)
    float* scand = (float*)(sm + 32768);                  // [32768, 45056)
    unsigned char* salive = (unsigned char*)(sm + 45056); // 512 B

    if (tid == 0) { s_cnt = g_cnt; s_nA = 0; }
    __syncthreads();
    u32 cnt = s_cnt; if (cnt > (u32)CAP) cnt = CAP;
    for (int i = tid; i < NK * 6; i += BLK) scand[i] = 0.f;
    if (tid < NK) salive[tid] = 0;
    float c1 = *c1p, c2 = *c2p;

    // pass 1: exact scores (bit-identical formula to the R4-passing kernel)
    for (u32 j = tid; j < cnt; j += BLK) {
        u32 id = ~(u32)g_gbuf[j];
        int S, a, b, cell;
        const float *src, *anc;
        map_id(id, o13, o26, o52, a13, a26, a52, S, src, anc, a, b, cell);
        int SS = S * S;
        const float* pc = src + (size_t)(b * 255 + a * 85) * SS + cell;
        float o0 = pc[0];
        float score = -1.f;
        u32 am = 0;
        if (o0 > 0.f) {
            float m = -1e30f, sum = 0.f; int amx = 0;
#pragma unroll 8
            for (int c = 0; c < 80; ++c) {
                float l = pc[(size_t)(5 + c) * SS];
                sum += expf(l);
                if (l > m) { m = l; amx = c; }
            }
            float obj = 1.f / (1.f + expf(-o0));
            score = obj * expf(m) / sum;
            am = (u32)amx;
        }
        skeys[j] = ((u64)fordf(score) << 32) | (u32)(~((id << 7) | am));
    }
    __syncthreads();

    // pass 2: exact ranks + box computation for ranks < 512
    for (u32 j = tid; j < cnt; j += BLK) {
        u64 kj = skeys[j];
        int r = 0; u32 i = 0;
        for (; i + 4 <= cnt; i += 4)
            r += (int)(skeys[i] > kj) + (int)(skeys[i+1] > kj)
               + (int)(skeys[i+2] > kj) + (int)(skeys[i+3] > kj);
        for (; i < cnt; ++i) r += (int)(skeys[i] > kj);
        if (r < NK && (u32)(kj >> 32) > 0x80000000u) {    // exact score > 0
            u32 v = ~(u32)kj;
            u32 id = v >> 7;
            int cls = (int)(v & 127u);
            int S, a, b, cell;
            const float *src, *anc;
            map_id(id, o13, o26, o52, a13, a26, a52, S, src, anc, a, b, cell);
            int SS = S * S;
            const float* pc = src + (size_t)(b * 255 + a * 85) * SS + cell;
            float o1 = pc[(size_t)SS],     o2 = pc[(size_t)2 * SS];
            float o3 = pc[(size_t)3 * SS], o4 = pc[(size_t)4 * SS];
            int y = cell / S, x = cell - y * S;
            float sc = 416.f / (float)S;
            float cx = ((float)x + o1) * sc / c1;
            float cy = ((float)y + o2) * sc / c2;
            float w  = expf(o3) * anc[2 * a] / c1;
            float h  = expf(o4) * anc[2 * a + 1] / c2;
            float p  = ifordf((u32)(kj >> 32));
            float* cd = scand + r * 6;
            cd[0] = p; cd[1] = cx; cd[2] = cy; cd[3] = w; cd[4] = h; cd[5] = (float)cls;
            salive[r] = 1;
        }
    }
    __syncthreads();

    // maxp over alive candidates
    {
        float p = 0.f;
        if (tid < NK && salive[tid]) p = scand[tid * 6];
        for (int o = 16; o > 0; o >>= 1) p = fmaxf(p, __shfl_xor_sync(0xffffffffu, p, o));
        if (lane == 0) s_red[tid >> 5] = p;
        __syncthreads();
        if (tid < 32) {
            float v = s_red[tid];
            for (int o = 16; o > 0; o >>= 1) v = fmaxf(v, __shfl_xor_sync(0xffffffffu, v, o));
            if (tid == 0) s_maxp = v;
        }
        __syncthreads();
    }

    // alive0 mask + compaction of alive rows
    if (tid < NK) {
        bool a0 = salive[tid] && (scand[tid * 6] > 0.5f * s_maxp);
        u32 m = __ballot_sync(0xffffffffu, a0);
        if (lane == 0) s_a0w[tid >> 5] = m;
        if (a0) {
            int k = atomicAdd(&s_nA, 1);
            s_aliveIdx[k] = tid;
            s_kOf[tid] = k;
        }
    }
    __syncthreads();

    // IoU suppress rows ONLY for alive0 candidates (reuse skeys region)
    u32* ssup = (u32*)sm;                     // nA*16 u32 <= 32 KB
    {
        int nA = s_nA;
        int w = tid >> 5;
        for (int k = w; k < nA; k += 32) {
            int i = s_aliveIdx[k];
            float cxi = scand[i*6+1], cyi = scand[i*6+2];
            float wi  = scand[i*6+3], hi  = scand[i*6+4], cli = scand[i*6+5];
            float x1i = cxi - wi * 0.5f, y1i = cyi - hi * 0.5f;
            float x2i = x1i + wi,        y2i = y1i + hi;
            float ai = (x2i - x1i) * (y2i - y1i);
            for (int cw = 0; cw < 16; ++cw) {
                int j = (cw << 5) + lane;
                const float* bj = scand + j * 6;
                float wj = bj[3], hj = bj[4];
                float x1j = bj[1] - wj * 0.5f, y1j = bj[2] - hj * 0.5f;
                float x2j = x1j + wj,          y2j = y1j + hj;
                float iw = fmaxf(fminf(x2i, x2j) - fmaxf(x1i, x1j), 0.f);
                float ih = fmaxf(fminf(y2i, y2j) - fmaxf(y1i, y1j), 0.f);
                float inter = iw * ih;
                float aj = (x2j - x1j) * (y2j - y1j);
                float iou = inter / (ai + aj - inter);
                bool sup = (cli == bj[5]) || (iou >= 0.5f);
                u32 msk = __ballot_sync(0xffffffffu, sup);
                if (lane == 0) ssup[k * 16 + cw] = msk;
            }
        }
    }
    __syncthreads();

    // serial cascade with ffs-skip (single thread; work ~ #keeps)
    if (tid == 0) {
        u32 sup[16], keep[16];
#pragma unroll
        for (int x = 0; x < 16; ++x) { sup[x] = ~s_a0w[x]; keep[x] = 0u; }
        for (int w = 0; w < 16; ++w) {
            u32 avail = ~sup[w];
            while (avail) {
                int bb = __ffs(avail) - 1;
                int i = (w << 5) + bb;
                keep[w] |= (1u << bb);
                int k = s_kOf[i];
#pragma unroll
                for (int x = 0; x < 16; ++x) sup[x] |= ssup[k * 16 + x];
                u32 hi = (bb == 31) ? 0u : (0xffffffffu << (bb + 1));
                avail = ~sup[w] & hi;
            }
        }
#pragma unroll
        for (int x = 0; x < 16; ++x) s_keep[x] = keep[x];
    }
    __syncthreads();

    // output
    if (tid < NK) {
        bool kp = (s_keep[tid >> 5] >> (tid & 31)) & 1u;
        float km = kp ? 1.f : 0.f;
        if (out_size >= NK * 6) {
#pragma unroll
            for (int c = 0; c < 6; ++c) out[tid * 6 + c] = scand[tid * 6 + c] * km;
        }
        if (out_size >= NK * 7) out[NK * 6 + tid] = km;
    }
}

// ---------------- launch: ONE kernel ------------------------------------------
extern "C" void kernel_launch(void* const* d_in, const int* in_sizes, int n_in,
                              void* d_out, int out_size) {
    k_mega<<<GRID, BLK>>>(
        (const float*)d_in[0], (const float*)d_in[1], (const float*)d_in[2],
        (const float*)d_in[3], (const float*)d_in[4], (const float*)d_in[5],
        (const float*)d_in[6], (const float*)d_in[7],
        (float*)d_out, out_size);
}

// round 7
// speedup vs baseline: 1.5525x; 1.4773x over previous
#include <cuda_runtime.h>
#include <cstdint>

typedef unsigned long long u64;
typedef unsigned u32;

#define N13   16224           // 32*3*169
#define N26   64896           // 32*3*676
#define N52   259584          // 32*3*2704
#define NT    340704
#define CAP   4096
#define NK    512
#define GRID  148
#define BLK   1024
#define NTH   (GRID*BLK)

#define G26OFF 16224          // key/id offset of scale-26 region
#define G52OFF 81120          // key/id offset of scale-52 region

#define W52 64896             // vec4 items for scale 52 (259584/4)
#define W26 16224             // vec4 items for scale 26 (64896/4)
#define W13 16224             // scalar items for scale 13
#define WTOT 97344            // total work items

// ---------------- scratch (static device globals: no allocation) ------------
__device__ u64   g_keys[NT];
__device__ float g_boxes[NT * 6];
__device__ u32   g_hist1[2048];
__device__ u32   g_hist2[2048];
__device__ u32   g_cnt;
__device__ u64   g_gbuf[CAP];
__device__ u32   g_bar_arrive;
__device__ u32   g_bar_gen;

__device__ __forceinline__ u32 fordf(float f) {
    u32 u = __float_as_uint(f);
    return (u & 0x80000000u) ? ~u : (u | 0x80000000u);
}

// grid barrier for k_rest: one block per SM (GRID=148, launch_bounds(1024,1))
__device__ __forceinline__ void grid_barrier() {
    __syncthreads();
    __threadfence();
    if (threadIdx.x == 0) {
        volatile u32* vgen = &g_bar_gen;
        u32 gen = *vgen;
        __threadfence();
        u32 a = atomicAdd(&g_bar_arrive, 1u);
        if (a == GRID - 1u) {
            g_bar_arrive = 0u;
            __threadfence();
            atomicAdd(&g_bar_gen, 1u);
        } else {
            while (*vgen == gen) {}
        }
    }
    __threadfence();
    __syncthreads();
}

// ---------------- decode: 4 consecutive cells per thread (vec4, precise) ----
template <int S, int GOFF>
__device__ __forceinline__ void decode_v4(int v,
                                          const float* __restrict__ out,
                                          const float* __restrict__ anc,
                                          float c1, float c2, u32* shist) {
    const int SS = S * S, G4 = SS / 4;
    int plane = v / G4;
    int grp = v - plane * G4;
    int cell0 = grp * 4;
    int b = plane / 3, a = plane - 3 * b;
    const float* pc = out + ((size_t)b * 255 + (size_t)a * 85) * SS + cell0;
    float4 q0 = *(const float4*)pc;
    float4 q1 = *(const float4*)(pc + SS);
    float4 q2 = *(const float4*)(pc + 2 * SS);
    float4 q3 = *(const float4*)(pc + 3 * SS);
    float4 q4 = *(const float4*)(pc + 4 * SS);
    float m0 = -1e30f, m1 = -1e30f, m2 = -1e30f, m3 = -1e30f;
    float s0 = 0.f, s1 = 0.f, s2 = 0.f, s3 = 0.f;
    int i0 = 0, i1 = 0, i2 = 0, i3 = 0;
#pragma unroll 4
    for (int c = 0; c < 80; ++c) {
        float4 l = *(const float4*)(pc + (size_t)(5 + c) * SS);
        s0 += expf(l.x); if (l.x > m0) { m0 = l.x; i0 = c; }
        s1 += expf(l.y); if (l.y > m1) { m1 = l.y; i1 = c; }
        s2 += expf(l.z); if (l.z > m2) { m2 = l.z; i2 = c; }
        s3 += expf(l.w); if (l.w > m3) { m3 = l.w; i3 = c; }
    }
    const float sc = 416.f / (float)S;
    float an0 = anc[2 * a], an1 = anc[2 * a + 1];
    float o0a[4] = {q0.x, q0.y, q0.z, q0.w};
    float o1a[4] = {q1.x, q1.y, q1.z, q1.w};
    float o2a[4] = {q2.x, q2.y, q2.z, q2.w};
    float o3a[4] = {q3.x, q3.y, q3.z, q3.w};
    float o4a[4] = {q4.x, q4.y, q4.z, q4.w};
    float ma[4] = {m0, m1, m2, m3};
    float sa[4] = {s0, s1, s2, s3};
    int   ia[4] = {i0, i1, i2, i3};
#pragma unroll
    for (int k = 0; k < 4; ++k) {
        int cell = cell0 + k;
        int g = GOFF + (b * SS + cell) * 3 + a;
        float score = -1.f;
        if (o0a[k] > 0.f) {
            float obj = 1.f / (1.f + expf(-o0a[k]));
            float p = obj * expf(ma[k]) / sa[k];
            int y = cell / S, x = cell - y * S;
            float cx = ((float)x + o1a[k]) * sc / c1;
            float cy = ((float)y + o2a[k]) * sc / c2;
            float w  = expf(o3a[k]) * an0 / c1;
            float h  = expf(o4a[k]) * an1 / c2;
            float* bx = g_boxes + (size_t)g * 6;
            bx[0] = p; bx[1] = cx; bx[2] = cy; bx[3] = w; bx[4] = h; bx[5] = (float)ia[k];
            score = p;
        }
        u32 fs = fordf(score);
        g_keys[GOFF + plane * SS + cell] = ((u64)fs << 32) | (u32)(~(u32)g);
        atomicAdd(&shist[fs >> 21], 1u);
    }
}

__device__ __forceinline__ void decode_s13(int v,
                                           const float* __restrict__ out,
                                           const float* __restrict__ anc,
                                           float c1, float c2, u32* shist) {
    const int S = 13, SS = 169;
    int plane = v / SS;
    int cell = v - plane * SS;
    int b = plane / 3, a = plane - 3 * b;
    const float* pc = out + ((size_t)b * 255 + (size_t)a * 85) * SS + cell;
    float o0 = pc[0];
    int g = (b * SS + cell) * 3 + a;     // GOFF = 0
    float score = -1.f;
    float m = -1e30f, sum = 0.f; int am = 0;
#pragma unroll 4
    for (int c = 0; c < 80; ++c) {
        float l = pc[(size_t)(5 + c) * SS];
        sum += expf(l);
        if (l > m) { m = l; am = c; }
    }
    if (o0 > 0.f) {
        float obj = 1.f / (1.f + expf(-o0));
        float p = obj * expf(m) / sum;
        int y = cell / S, x = cell - y * S;
        const float sc = 416.f / 13.f;
        float cx = ((float)x + pc[SS]) * sc / c1;
        float cy = ((float)y + pc[2 * SS]) * sc / c2;
        float w  = expf(pc[3 * SS]) * anc[2 * a] / c1;
        float h  = expf(pc[4 * SS]) * anc[2 * a + 1] / c2;
        float* bx = g_boxes + (size_t)g * 6;
        bx[0] = p; bx[1] = cx; bx[2] = cy; bx[3] = w; bx[4] = h; bx[5] = (float)am;
        score = p;
    }
    u32 fs = fordf(score);
    g_keys[plane * SS + cell] = ((u64)fs << 32) | (u32)(~(u32)g);
    atomicAdd(&shist[fs >> 21], 1u);
}

// ---------------- kernel 1: decode (high occupancy, static partition) --------
__global__ void __launch_bounds__(256) k_decode(
    const float* __restrict__ o13, const float* __restrict__ o26,
    const float* __restrict__ o52,
    const float* __restrict__ a13, const float* __restrict__ a26,
    const float* __restrict__ a52,
    const float* __restrict__ c1p, const float* __restrict__ c2p)
{
    __shared__ u32 shist[2048];
    for (int i = threadIdx.x; i < 2048; i += 256) shist[i] = 0;
    if (blockIdx.x == 0 && threadIdx.x == 0) g_cnt = 0;   // consumed only in k_rest
    __syncthreads();
    int item = blockIdx.x * 256 + threadIdx.x;
    float c1 = *c1p, c2 = *c2p;
    if (item < WTOT) {
        if (item < W52)            decode_v4<52, G52OFF>(item, o52, a52, c1, c2, shist);
        else if (item < W52 + W26) decode_v4<26, G26OFF>(item - W52, o26, a26, c1, c2, shist);
        else                       decode_s13(item - (W52 + W26), o13, a13, c1, c2, shist);
    }
    __syncthreads();
    for (int i = threadIdx.x; i < 2048; i += 256) {
        u32 v = shist[i];
        if (v) atomicAdd(&g_hist1[i], v);
    }
}

// suffix scan of a 2048-bin histogram; find threshold bucket
__device__ __forceinline__ void suffix_select(u32* sa, u32* sb, const u32* ghist,
                                              u32 target, int* out_b, u32* out_above) {
    int tid = threadIdx.x;
    for (int i = tid; i < 2048; i += BLK) sa[i] = ghist[i];
    __syncthreads();
    u32 *src = sa, *dst = sb;
    for (int off = 1; off < 2048; off <<= 1) {
        for (int i = tid; i < 2048; i += BLK) {
            u32 v = src[i];
            if (i + off < 2048) v += src[i + off];
            dst[i] = v;
        }
        __syncthreads();
        u32* tmp = src; src = dst; dst = tmp;
    }
    for (int i = tid; i < 2048; i += BLK) {
        bool cross = (src[i] >= target) && (i == 2047 || src[i + 1] < target);
        if (cross) {
            *out_b = i;
            if (out_above) *out_above = (i == 2047) ? 0u : src[i + 1];
        }
    }
    __syncthreads();
}

// ---------------- kernel 2: select + gather + NMS + output -------------------
__global__ void __launch_bounds__(BLK, 1) k_rest(float* __restrict__ out, int out_size)
{
    __shared__ __align__(16) unsigned char sm[47104];
    __shared__ int   s_b1, s_b2;
    __shared__ u32   s_cA1;
    __shared__ u32   s_cnt;
    __shared__ u32   s_a0w[16], s_keep[16];
    __shared__ int   s_aliveIdx[NK];
    __shared__ int   s_kOf[NK];
    __shared__ int   s_nA;
    __shared__ float s_red[32];
    __shared__ float s_maxp;

    const int tid = threadIdx.x;
    const int gt = blockIdx.x * BLK + tid;
    const int lane = tid & 31;

    // ===== P2+P3: every block selects b1 (redundantly), then builds hist2 =====
    {
        u32* sa = (u32*)sm; u32* sb = sa + 2048;
        suffix_select(sa, sb, g_hist1, (u32)NK, &s_b1, &s_cA1);
        u32* sh2 = (u32*)sm;
        for (int i = tid; i < 2048; i += BLK) sh2[i] = 0;
        __syncthreads();
        int B1 = s_b1;
        for (int t = gt; t < NT; t += NTH) {
            u64 k = g_keys[t];
            if ((int)(u32)(k >> 53) == B1)
                atomicAdd(&sh2[(u32)(k >> 42) & 2047u], 1u);
        }
        __syncthreads();
        for (int i = tid; i < 2048; i += BLK) {
            u32 v = sh2[i];
            if (v) atomicAdd(&g_hist2[i], v);
        }
    }
    grid_barrier();

    // ===== P4+P5: every block selects b2, then gathers candidates =====
    {
        u32* sa = (u32*)sm; u32* sb = sa + 2048;
        suffix_select(sa, sb, g_hist2, (u32)NK - s_cA1, &s_b2, 0);
        int B1 = s_b1, B2 = s_b2;
        for (int t = gt; t < NT; t += NTH) {
            u64 k = g_keys[t];
            int b1 = (int)(u32)(k >> 53);
            int b2 = (int)((u32)(k >> 42) & 2047u);
            if (b1 > B1 || (b1 == B1 && b2 >= B2)) {
                u32 pos = atomicAdd(&g_cnt, 1u);
                if (pos < (u32)CAP) g_gbuf[pos] = k;
            }
        }
    }
    grid_barrier();   // last barrier

    // tail-fill of out beyond 512*7 (disjoint from block-0 writes)
    for (int i = NK * 7 + gt; i < out_size; i += NTH) out[i] = 0.f;

    if (blockIdx.x == 1) {          // scratch reset for next graph replay
        for (int i = tid; i < 2048; i += BLK) { g_hist1[i] = 0; g_hist2[i] = 0; }
    }
    if (blockIdx.x != 0) return;

    // =================== block 0: rank-select + NMS + output ===================
    u64*   skeys = (u64*)sm;                              // [0, 32768)
    float* scand = (float*)(sm + 32768);                  // [32768, 45056)
    unsigned char* salive = (unsigned char*)(sm + 45056); // 512 B

    if (tid == 0) { s_cnt = g_cnt; s_nA = 0; }
    __syncthreads();
    u32 cnt = s_cnt; if (cnt > (u32)CAP) cnt = CAP;
    for (u32 i = tid; i < cnt; i += BLK) skeys[i] = g_gbuf[i];
    for (int i = tid; i < NK * 6; i += BLK) scand[i] = 0.f;
    if (tid < NK) salive[tid] = 0;
    __syncthreads();

    // exact ranks (keys unique), fill candidate table
    for (u32 j = tid; j < cnt; j += BLK) {
        u64 kj = skeys[j];
        int r = 0; u32 i = 0;
        for (; i + 4 <= cnt; i += 4)
            r += (int)(skeys[i] > kj) + (int)(skeys[i+1] > kj)
               + (int)(skeys[i+2] > kj) + (int)(skeys[i+3] > kj);
        for (; i < cnt; ++i) r += (int)(skeys[i] > kj);
        if (r < NK && (u32)(kj >> 32) > 0x80000000u) {   // score > 0
            u32 g = ~(u32)kj;
            const float* bx = g_boxes + (size_t)g * 6;
            float* cd = scand + r * 6;
            cd[0] = bx[0]; cd[1] = bx[1]; cd[2] = bx[2];
            cd[3] = bx[3]; cd[4] = bx[4]; cd[5] = bx[5];
            salive[r] = 1;
        }
    }
    __syncthreads();

    // maxp over alive candidates
    {
        float p = 0.f;
        if (tid < NK && salive[tid]) p = scand[tid * 6];
        for (int o = 16; o > 0; o >>= 1) p = fmaxf(p, __shfl_xor_sync(0xffffffffu, p, o));
        if (lane == 0) s_red[tid >> 5] = p;
        __syncthreads();
        if (tid < 32) {
            float v = s_red[tid];
            for (int o = 16; o > 0; o >>= 1) v = fmaxf(v, __shfl_xor_sync(0xffffffffu, v, o));
            if (tid == 0) s_maxp = v;
        }
        __syncthreads();
    }

    // alive0 mask + compaction of alive rows
    if (tid < NK) {
        bool a0 = salive[tid] && (scand[tid * 6] > 0.5f * s_maxp);
        u32 m = __ballot_sync(0xffffffffu, a0);
        if (lane == 0) s_a0w[tid >> 5] = m;
        if (a0) {
            int k = atomicAdd(&s_nA, 1);
            s_aliveIdx[k] = tid;
            s_kOf[tid] = k;
        }
    }
    __syncthreads();

    // IoU suppress rows ONLY for alive0 candidates (reuse skeys region)
    u32* ssup = (u32*)sm;
    {
        int nA = s_nA;
        int w = tid >> 5;
        for (int k = w; k < nA; k += 32) {
            int i = s_aliveIdx[k];
            float cxi = scand[i*6+1], cyi = scand[i*6+2];
            float wi  = scand[i*6+3], hi  = scand[i*6+4], cli = scand[i*6+5];
            float x1i = cxi - wi * 0.5f, y1i = cyi - hi * 0.5f;
            float x2i = x1i + wi,        y2i = y1i + hi;
            float ai = (x2i - x1i) * (y2i - y1i);
            for (int cw = 0; cw < 16; ++cw) {
                int j = (cw << 5) + lane;
                const float* bj = scand + j * 6;
                float wj = bj[3], hj = bj[4];
                float x1j = bj[1] - wj * 0.5f, y1j = bj[2] - hj * 0.5f;
                float x2j = x1j + wj,          y2j = y1j + hj;
                float iw = fmaxf(fminf(x2i, x2j) - fmaxf(x1i, x1j), 0.f);
                float ih = fmaxf(fminf(y2i, y2j) - fmaxf(y1i, y1j), 0.f);
                float inter = iw * ih;
                float aj = (x2j - x1j) * (y2j - y1j);
                float iou = inter / (ai + aj - inter);
                bool sup = (cli == bj[5]) || (iou >= 0.5f);
                u32 msk = __ballot_sync(0xffffffffu, sup);
                if (lane == 0) ssup[k * 16 + cw] = msk;
            }
        }
    }
    __syncthreads();

    // serial cascade with ffs-skip (single thread; work ~ #keeps)
    if (tid == 0) {
        u32 sup[16], keep[16];
#pragma unroll
        for (int x = 0; x < 16; ++x) { sup[x] = ~s_a0w[x]; keep[x] = 0u; }
        for (int w = 0; w < 16; ++w) {
            u32 avail = ~sup[w];
            while (avail) {
                int bb = __ffs(avail) - 1;
                int i = (w << 5) + bb;
                keep[w] |= (1u << bb);
                int k = s_kOf[i];
#pragma unroll
                for (int x = 0; x < 16; ++x) sup[x] |= ssup[k * 16 + x];
                u32 hi = (bb == 31) ? 0u : (0xffffffffu << (bb + 1));
                avail = ~sup[w] & hi;
            }
        }
#pragma unroll
        for (int x = 0; x < 16; ++x) s_keep[x] = keep[x];
    }
    __syncthreads();

    // output
    if (tid < NK) {
        bool kp = (s_keep[tid >> 5] >> (tid & 31)) & 1u;
        float km = kp ? 1.f : 0.f;
        if (out_size >= NK * 6) {
#pragma unroll
            for (int c = 0; c < 6; ++c) out[tid * 6 + c] = scand[tid * 6 + c] * km;
        }
        if (out_size >= NK * 7) out[NK * 6 + tid] = km;
    }
}

// ---------------- launch: TWO kernels (per-phase ncu attribution) -------------
extern "C" void kernel_launch(void* const* d_in, const int* in_sizes, int n_in,
                              void* d_out, int out_size) {
    k_decode<<<(WTOT + 255) / 256, 256>>>(
        (const float*)d_in[0], (const float*)d_in[1], (const float*)d_in[2],
        (const float*)d_in[3], (const float*)d_in[4], (const float*)d_in[5],
        (const float*)d_in[6], (const float*)d_in[7]);
    k_rest<<<GRID, BLK>>>((float*)d_out, out_size);
}

// round 8
// speedup vs baseline: 1.5589x; 1.0041x over previous
#include <cuda_runtime.h>
#include <cstdint>

typedef unsigned long long u64;
typedef unsigned u32;

#define N13   16224           // 32*3*169
#define N26   64896           // 32*3*676
#define N52   259584          // 32*3*2704
#define NT    340704
#define CAP   4096
#define NK    512
#define GRID  148
#define BLK   1024
#define NTH   (GRID*BLK)

#define G26OFF 16224
#define G52OFF 81120

#define W52 64896             // vec4 items for scale 52
#define W26 16224             // vec4 items for scale 26
#define W13 16224             // scalar items for scale 13
#define WTOT 97344

// ---------------- scratch (static device globals: no allocation) ------------
__device__ u64   g_keys[NT];
__device__ float g_boxes[NT * 6];
__device__ u32   g_hist1[2048];
__device__ u32   g_hist2[2048];
__device__ u32   g_cnt;
__device__ int   g_b1g;
__device__ u32   g_cA1g;
__device__ u64   g_gbuf[CAP];

__device__ __forceinline__ u32 fordf(float f) {
    u32 u = __float_as_uint(f);
    return (u & 0x80000000u) ? ~u : (u | 0x80000000u);
}

// ---------------- decode: 4 consecutive cells per thread (vec4, precise) ----
template <int S, int GOFF>
__device__ __forceinline__ void decode_v4(int v,
                                          const float* __restrict__ out,
                                          const float* __restrict__ anc,
                                          float c1, float c2, u32* shist) {
    const int SS = S * S, G4 = SS / 4;
    int plane = v / G4;
    int grp = v - plane * G4;
    int cell0 = grp * 4;
    int b = plane / 3, a = plane - 3 * b;
    const float* pc = out + ((size_t)b * 255 + (size_t)a * 85) * SS + cell0;
    float4 q0 = *(const float4*)pc;
    float4 q1 = *(const float4*)(pc + SS);
    float4 q2 = *(const float4*)(pc + 2 * SS);
    float4 q3 = *(const float4*)(pc + 3 * SS);
    float4 q4 = *(const float4*)(pc + 4 * SS);
    float m0 = -1e30f, m1 = -1e30f, m2 = -1e30f, m3 = -1e30f;
    float s0 = 0.f, s1 = 0.f, s2 = 0.f, s3 = 0.f;
    int i0 = 0, i1 = 0, i2 = 0, i3 = 0;
#pragma unroll 4
    for (int c = 0; c < 80; ++c) {
        float4 l = *(const float4*)(pc + (size_t)(5 + c) * SS);
        s0 += expf(l.x); if (l.x > m0) { m0 = l.x; i0 = c; }
        s1 += expf(l.y); if (l.y > m1) { m1 = l.y; i1 = c; }
        s2 += expf(l.z); if (l.z > m2) { m2 = l.z; i2 = c; }
        s3 += expf(l.w); if (l.w > m3) { m3 = l.w; i3 = c; }
    }
    const float sc = 416.f / (float)S;
    float an0 = anc[2 * a], an1 = anc[2 * a + 1];
    float o0a[4] = {q0.x, q0.y, q0.z, q0.w};
    float o1a[4] = {q1.x, q1.y, q1.z, q1.w};
    float o2a[4] = {q2.x, q2.y, q2.z, q2.w};
    float o3a[4] = {q3.x, q3.y, q3.z, q3.w};
    float o4a[4] = {q4.x, q4.y, q4.z, q4.w};
    float ma[4] = {m0, m1, m2, m3};
    float sa[4] = {s0, s1, s2, s3};
    int   ia[4] = {i0, i1, i2, i3};
#pragma unroll
    for (int k = 0; k < 4; ++k) {
        int cell = cell0 + k;
        int g = GOFF + (b * SS + cell) * 3 + a;
        float score = -1.f;
        if (o0a[k] > 0.f) {
            float obj = 1.f / (1.f + expf(-o0a[k]));
            float p = obj * expf(ma[k]) / sa[k];
            int y = cell / S, x = cell - y * S;
            float cx = ((float)x + o1a[k]) * sc / c1;
            float cy = ((float)y + o2a[k]) * sc / c2;
            float w  = expf(o3a[k]) * an0 / c1;
            float h  = expf(o4a[k]) * an1 / c2;
            float* bx = g_boxes + (size_t)g * 6;
            bx[0] = p; bx[1] = cx; bx[2] = cy; bx[3] = w; bx[4] = h; bx[5] = (float)ia[k];
            score = p;
        }
        u32 fs = fordf(score);
        g_keys[GOFF + plane * SS + cell] = ((u64)fs << 32) | (u32)(~(u32)g);
        atomicAdd(&shist[fs >> 21], 1u);
    }
}

__device__ __forceinline__ void decode_s13(int v,
                                           const float* __restrict__ out,
                                           const float* __restrict__ anc,
                                           float c1, float c2, u32* shist) {
    const int S = 13, SS = 169;
    int plane = v / SS;
    int cell = v - plane * SS;
    int b = plane / 3, a = plane - 3 * b;
    const float* pc = out + ((size_t)b * 255 + (size_t)a * 85) * SS + cell;
    float o0 = pc[0];
    int g = (b * SS + cell) * 3 + a;
    float score = -1.f;
    float m = -1e30f, sum = 0.f; int am = 0;
#pragma unroll 4
    for (int c = 0; c < 80; ++c) {
        float l = pc[(size_t)(5 + c) * SS];
        sum += expf(l);
        if (l > m) { m = l; am = c; }
    }
    if (o0 > 0.f) {
        float obj = 1.f / (1.f + expf(-o0));
        float p = obj * expf(m) / sum;
        int y = cell / S, x = cell - y * S;
        const float sc = 416.f / 13.f;
        float cx = ((float)x + pc[SS]) * sc / c1;
        float cy = ((float)y + pc[2 * SS]) * sc / c2;
        float w  = expf(pc[3 * SS]) * anc[2 * a] / c1;
        float h  = expf(pc[4 * SS]) * anc[2 * a + 1] / c2;
        float* bx = g_boxes + (size_t)g * 6;
        bx[0] = p; bx[1] = cx; bx[2] = cy; bx[3] = w; bx[4] = h; bx[5] = (float)am;
        score = p;
    }
    u32 fs = fordf(score);
    g_keys[plane * SS + cell] = ((u64)fs << 32) | (u32)(~(u32)g);
    atomicAdd(&shist[fs >> 21], 1u);
}

// ---------------- kernel 1: decode ------------------------------------------
__global__ void __launch_bounds__(256) k_decode(
    const float* __restrict__ o13, const float* __restrict__ o26,
    const float* __restrict__ o52,
    const float* __restrict__ a13, const float* __restrict__ a26,
    const float* __restrict__ a52,
    const float* __restrict__ c1p, const float* __restrict__ c2p)
{
    __shared__ u32 shist[2048];
    for (int i = threadIdx.x; i < 2048; i += 256) shist[i] = 0;
    if (blockIdx.x == 0 && threadIdx.x == 0) g_cnt = 0;
    __syncthreads();
    int item = blockIdx.x * 256 + threadIdx.x;
    float c1 = *c1p, c2 = *c2p;
    if (item < WTOT) {
        if (item < W52)            decode_v4<52, G52OFF>(item, o52, a52, c1, c2, shist);
        else if (item < W52 + W26) decode_v4<26, G26OFF>(item - W52, o26, a26, c1, c2, shist);
        else                       decode_s13(item - (W52 + W26), o13, a13, c1, c2, shist);
    }
    __syncthreads();
    for (int i = threadIdx.x; i < 2048; i += 256) {
        u32 v = shist[i];
        if (v) atomicAdd(&g_hist1[i], v);
    }
}

// suffix scan of a 2048-bin histogram; find threshold bucket (1024 threads)
__device__ __forceinline__ void suffix_select(u32* sa, u32* sb, const u32* ghist,
                                              u32 target, int* out_b, u32* out_above) {
    int tid = threadIdx.x;
    for (int i = tid; i < 2048; i += BLK) sa[i] = ghist[i];
    __syncthreads();
    u32 *src = sa, *dst = sb;
    for (int off = 1; off < 2048; off <<= 1) {
        for (int i = tid; i < 2048; i += BLK) {
            u32 v = src[i];
            if (i + off < 2048) v += src[i + off];
            dst[i] = v;
        }
        __syncthreads();
        u32* tmp = src; src = dst; dst = tmp;
    }
    for (int i = tid; i < 2048; i += BLK) {
        bool cross = (src[i] >= target) && (i == 2047 || src[i + 1] < target);
        if (cross) {
            *out_b = i;
            if (out_above) *out_above = (i == 2047) ? 0u : src[i + 1];
        }
    }
    __syncthreads();
}

// ---------------- kernel 2: select1 + hist2 ----------------------------------
__global__ void __launch_bounds__(BLK) k_mid()
{
    __shared__ u32 sa[2048], sb[2048];
    __shared__ int s_b1;
    __shared__ u32 s_cA1;
    const int tid = threadIdx.x;
    const int gt = blockIdx.x * BLK + tid;

    suffix_select(sa, sb, g_hist1, (u32)NK, &s_b1, &s_cA1);
    if (blockIdx.x == 0 && tid == 0) { g_b1g = s_b1; g_cA1g = s_cA1; }

    // hist2 over keys in bucket b1 (shared-first)
    for (int i = tid; i < 2048; i += BLK) sa[i] = 0;
    __syncthreads();
    int B1 = s_b1;
    for (int t = gt; t < NT; t += NTH) {
        u64 k = g_keys[t];
        if ((int)(u32)(k >> 53) == B1)
            atomicAdd(&sa[(u32)(k >> 42) & 2047u], 1u);
    }
    __syncthreads();
    for (int i = tid; i < 2048; i += BLK) {
        u32 v = sa[i];
        if (v) atomicAdd(&g_hist2[i], v);
    }
}

// ---------------- kernel 3: select2 + gather ----------------------------------
__global__ void __launch_bounds__(BLK) k_gather()
{
    __shared__ u32 sa[2048], sb[2048];
    __shared__ int s_b2;
    const int tid = threadIdx.x;
    const int gt = blockIdx.x * BLK + tid;

    int B1 = g_b1g;
    u32 cA1 = g_cA1g;
    suffix_select(sa, sb, g_hist2, (u32)NK - cA1, &s_b2, 0);
    int B2 = s_b2;
    for (int t = gt; t < NT; t += NTH) {
        u64 k = g_keys[t];
        int b1 = (int)(u32)(k >> 53);
        int b2 = (int)((u32)(k >> 42) & 2047u);
        if (b1 > B1 || (b1 == B1 && b2 >= B2)) {
            u32 pos = atomicAdd(&g_cnt, 1u);
            if (pos < (u32)CAP) g_gbuf[pos] = k;
        }
    }
    // reset hist1 for next graph replay (no longer read this replay)
    if (blockIdx.x == 1)
        for (int i = tid; i < 2048; i += BLK) g_hist1[i] = 0;
}

// ---------------- kernel 4: rank-select + NMS + output (single block) --------
__global__ void __launch_bounds__(BLK) k_tail(float* __restrict__ out, int out_size)
{
    __shared__ __align__(16) unsigned char sm[47104];
    __shared__ u32   s_cnt;
    __shared__ u32   s_a0w[16], s_keep[16];
    __shared__ int   s_aliveIdx[NK];
    __shared__ int   s_kOf[NK];
    __shared__ int   s_nA;
    __shared__ float s_red[32];
    __shared__ float s_maxp;

    const int tid = threadIdx.x;
    const int lane = tid & 31;

    u64*   skeys = (u64*)sm;                              // [0, 32768)
    float* scand = (float*)(sm + 32768);                  // [32768, 45056)
    unsigned char* salive = (unsigned char*)(sm + 45056); // 512 B

    if (tid == 0) { s_cnt = g_cnt; s_nA = 0; }
    // reset hist2 for next replay (read only in k_gather, a prior node)
    for (int i = tid; i < 2048; i += BLK) g_hist2[i] = 0;
    // tail-fill of out beyond 512*7
    for (int i = NK * 7 + tid; i < out_size; i += BLK) out[i] = 0.f;
    __syncthreads();
    u32 cnt = s_cnt; if (cnt > (u32)CAP) cnt = CAP;
    for (u32 i = tid; i < cnt; i += BLK) skeys[i] = g_gbuf[i];
    for (int i = tid; i < NK * 6; i += BLK) scand[i] = 0.f;
    if (tid < NK) salive[tid] = 0;
    __syncthreads();

    // exact ranks (keys unique), fill candidate table
    for (u32 j = tid; j < cnt; j += BLK) {
        u64 kj = skeys[j];
        int r = 0; u32 i = 0;
        for (; i + 4 <= cnt; i += 4)
            r += (int)(skeys[i] > kj) + (int)(skeys[i+1] > kj)
               + (int)(skeys[i+2] > kj) + (int)(skeys[i+3] > kj);
        for (; i < cnt; ++i) r += (int)(skeys[i] > kj);
        if (r < NK && (u32)(kj >> 32) > 0x80000000u) {
            u32 g = ~(u32)kj;
            const float* bx = g_boxes + (size_t)g * 6;
            float* cd = scand + r * 6;
            cd[0] = bx[0]; cd[1] = bx[1]; cd[2] = bx[2];
            cd[3] = bx[3]; cd[4] = bx[4]; cd[5] = bx[5];
            salive[r] = 1;
        }
    }
    __syncthreads();

    // maxp over alive candidates
    {
        float p = 0.f;
        if (tid < NK && salive[tid]) p = scand[tid * 6];
        for (int o = 16; o > 0; o >>= 1) p = fmaxf(p, __shfl_xor_sync(0xffffffffu, p, o));
        if (lane == 0) s_red[tid >> 5] = p;
        __syncthreads();
        if (tid < 32) {
            float v = s_red[tid];
            for (int o = 16; o > 0; o >>= 1) v = fmaxf(v, __shfl_xor_sync(0xffffffffu, v, o));
            if (tid == 0) s_maxp = v;
        }
        __syncthreads();
    }

    // alive0 mask + compaction of alive rows
    if (tid < NK) {
        bool a0 = salive[tid] && (scand[tid * 6] > 0.5f * s_maxp);
        u32 m = __ballot_sync(0xffffffffu, a0);
        if (lane == 0) s_a0w[tid >> 5] = m;
        if (a0) {
            int k = atomicAdd(&s_nA, 1);
            s_aliveIdx[k] = tid;
            s_kOf[tid] = k;
        }
    }
    __syncthreads();

    // IoU suppress rows ONLY for alive0 candidates (reuse skeys region)
    u32* ssup = (u32*)sm;
    {
        int nA = s_nA;
        int w = tid >> 5;
        for (int k = w; k < nA; k += 32) {
            int i = s_aliveIdx[k];
            float cxi = scand[i*6+1], cyi = scand[i*6+2];
            float wi  = scand[i*6+3], hi  = scand[i*6+4], cli = scand[i*6+5];
            float x1i = cxi - wi * 0.5f, y1i = cyi - hi * 0.5f;
            float x2i = x1i + wi,        y2i = y1i + hi;
            float ai = (x2i - x1i) * (y2i - y1i);
            for (int cw = 0; cw < 16; ++cw) {
                int j = (cw << 5) + lane;
                const float* bj = scand + j * 6;
                float wj = bj[3], hj = bj[4];
                float x1j = bj[1] - wj * 0.5f, y1j = bj[2] - hj * 0.5f;
                float x2j = x1j + wj,          y2j = y1j + hj;
                float iw = fmaxf(fminf(x2i, x2j) - fmaxf(x1i, x1j), 0.f);
                float ih = fmaxf(fminf(y2i, y2j) - fmaxf(y1i, y1j), 0.f);
                float inter = iw * ih;
                float aj = (x2j - x1j) * (y2j - y1j);
                float iou = inter / (ai + aj - inter);
                bool sup = (cli == bj[5]) || (iou >= 0.5f);
                u32 msk = __ballot_sync(0xffffffffu, sup);
                if (lane == 0) ssup[k * 16 + cw] = msk;
            }
        }
    }
    __syncthreads();

    // serial cascade with ffs-skip (single thread; work ~ #keeps)
    if (tid == 0) {
        u32 sup[16], keep[16];
#pragma unroll
        for (int x = 0; x < 16; ++x) { sup[x] = ~s_a0w[x]; keep[x] = 0u; }
        for (int w = 0; w < 16; ++w) {
            u32 avail = ~sup[w];
            while (avail) {
                int bb = __ffs(avail) - 1;
                int i = (w << 5) + bb;
                keep[w] |= (1u << bb);
                int k = s_kOf[i];
#pragma unroll
                for (int x = 0; x < 16; ++x) sup[x] |= ssup[k * 16 + x];
                u32 hi = (bb == 31) ? 0u : (0xffffffffu << (bb + 1));
                avail = ~sup[w] & hi;
            }
        }
#pragma unroll
        for (int x = 0; x < 16; ++x) s_keep[x] = keep[x];
    }
    __syncthreads();

    // output
    if (tid < NK) {
        bool kp = (s_keep[tid >> 5] >> (tid & 31)) & 1u;
        float km = kp ? 1.f : 0.f;
        if (out_size >= NK * 6) {
#pragma unroll
            for (int c = 0; c < 6; ++c) out[tid * 6 + c] = scand[tid * 6 + c] * km;
        }
        if (out_size >= NK * 7) out[NK * 6 + tid] = km;
    }
}

// ---------------- launch: FOUR kernels (graph-serialized, no spin barriers) ---
extern "C" void kernel_launch(void* const* d_in, const int* in_sizes, int n_in,
                              void* d_out, int out_size) {
    k_decode<<<(WTOT + 255) / 256, 256>>>(
        (const float*)d_in[0], (const float*)d_in[1], (const float*)d_in[2],
        (const float*)d_in[3], (const float*)d_in[4], (const float*)d_in[5],
        (const float*)d_in[6], (const float*)d_in[7]);
    k_mid<<<GRID, BLK>>>();
    k_gather<<<GRID, BLK>>>();
    k_tail<<<1, BLK>>>((float*)d_out, out_size);
}

// round 9
// speedup vs baseline: 2.0338x; 1.3047x over previous
#include <cuda_runtime.h>
#include <cstdint>

typedef unsigned long long u64;
typedef unsigned u32;

#define N13   16224
#define N26   64896
#define N52   259584
#define NT    340704
#define CAP   4096
#define NK    512
#define GRID  148
#define BLK   1024
#define NTH   (GRID*BLK)

#define G26OFF 16224
#define G52OFF 81120

#define W52 64896
#define W26 16224
#define W13 16224
#define WTOT 97344

// ---------------- scratch (static device globals: no allocation) ------------
__device__ u64   g_keys[NT];
__device__ float g_boxes[NT * 6];
__device__ u32   g_hist1[2048];
__device__ u32   g_hist2[2048];
__device__ u32   g_cnt;
__device__ int   g_b1g;
__device__ u32   g_cA1g;
__device__ u64   g_gbuf[CAP];
__device__ float g_cand[NK * 6];
__device__ unsigned char g_alive[NK];
__device__ float g_maxp;
__device__ u32   g_sup[NK * 16];

__device__ __forceinline__ u32 fordf(float f) {
    u32 u = __float_as_uint(f);
    return (u & 0x80000000u) ? ~u : (u | 0x80000000u);
}
__device__ __forceinline__ float ifordf(u32 e) {
    return __uint_as_float((e & 0x80000000u) ? (e & 0x7fffffffu) : ~e);
}

// ---------------- decode: 4 consecutive cells per thread (vec4, precise) ----
template <int S, int GOFF>
__device__ __forceinline__ void decode_v4(int v,
                                          const float* __restrict__ out,
                                          const float* __restrict__ anc,
                                          float c1, float c2, u32* shist) {
    const int SS = S * S, G4 = SS / 4;
    int plane = v / G4;
    int grp = v - plane * G4;
    int cell0 = grp * 4;
    int b = plane / 3, a = plane - 3 * b;
    const float* pc = out + ((size_t)b * 255 + (size_t)a * 85) * SS + cell0;
    float4 q0 = *(const float4*)pc;
    float4 q1 = *(const float4*)(pc + SS);
    float4 q2 = *(const float4*)(pc + 2 * SS);
    float4 q3 = *(const float4*)(pc + 3 * SS);
    float4 q4 = *(const float4*)(pc + 4 * SS);
    float m0 = -1e30f, m1 = -1e30f, m2 = -1e30f, m3 = -1e30f;
    float s0 = 0.f, s1 = 0.f, s2 = 0.f, s3 = 0.f;
    int i0 = 0, i1 = 0, i2 = 0, i3 = 0;
#pragma unroll 4
    for (int c = 0; c < 80; ++c) {
        float4 l = *(const float4*)(pc + (size_t)(5 + c) * SS);
        s0 += expf(l.x); if (l.x > m0) { m0 = l.x; i0 = c; }
        s1 += expf(l.y); if (l.y > m1) { m1 = l.y; i1 = c; }
        s2 += expf(l.z); if (l.z > m2) { m2 = l.z; i2 = c; }
        s3 += expf(l.w); if (l.w > m3) { m3 = l.w; i3 = c; }
    }
    const float sc = 416.f / (float)S;
    float an0 = anc[2 * a], an1 = anc[2 * a + 1];
    float o0a[4] = {q0.x, q0.y, q0.z, q0.w};
    float o1a[4] = {q1.x, q1.y, q1.z, q1.w};
    float o2a[4] = {q2.x, q2.y, q2.z, q2.w};
    float o3a[4] = {q3.x, q3.y, q3.z, q3.w};
    float o4a[4] = {q4.x, q4.y, q4.z, q4.w};
    float ma[4] = {m0, m1, m2, m3};
    float sa[4] = {s0, s1, s2, s3};
    int   ia[4] = {i0, i1, i2, i3};
#pragma unroll
    for (int k = 0; k < 4; ++k) {
        int cell = cell0 + k;
        int g = GOFF + (b * SS + cell) * 3 + a;
        float score = -1.f;
        if (o0a[k] > 0.f) {
            float obj = 1.f / (1.f + expf(-o0a[k]));
            float p = obj * expf(ma[k]) / sa[k];
            int y = cell / S, x = cell - y * S;
            float cx = ((float)x + o1a[k]) * sc / c1;
            float cy = ((float)y + o2a[k]) * sc / c2;
            float w  = expf(o3a[k]) * an0 / c1;
            float h  = expf(o4a[k]) * an1 / c2;
            float* bx = g_boxes + (size_t)g * 6;
            bx[0] = p; bx[1] = cx; bx[2] = cy; bx[3] = w; bx[4] = h; bx[5] = (float)ia[k];
            score = p;
        }
        u32 fs = fordf(score);
        g_keys[GOFF + plane * SS + cell] = ((u64)fs << 32) | (u32)(~(u32)g);
        atomicAdd(&shist[fs >> 21], 1u);
    }
}

__device__ __forceinline__ void decode_s13(int v,
                                           const float* __restrict__ out,
                                           const float* __restrict__ anc,
                                           float c1, float c2, u32* shist) {
    const int S = 13, SS = 169;
    int plane = v / SS;
    int cell = v - plane * SS;
    int b = plane / 3, a = plane - 3 * b;
    const float* pc = out + ((size_t)b * 255 + (size_t)a * 85) * SS + cell;
    float o0 = pc[0];
    int g = (b * SS + cell) * 3 + a;
    float score = -1.f;
    float m = -1e30f, sum = 0.f; int am = 0;
#pragma unroll 4
    for (int c = 0; c < 80; ++c) {
        float l = pc[(size_t)(5 + c) * SS];
        sum += expf(l);
        if (l > m) { m = l; am = c; }
    }
    if (o0 > 0.f) {
        float obj = 1.f / (1.f + expf(-o0));
        float p = obj * expf(m) / sum;
        int y = cell / S, x = cell - y * S;
        const float sc = 416.f / 13.f;
        float cx = ((float)x + pc[SS]) * sc / c1;
        float cy = ((float)y + pc[2 * SS]) * sc / c2;
        float w  = expf(pc[3 * SS]) * anc[2 * a] / c1;
        float h  = expf(pc[4 * SS]) * anc[2 * a + 1] / c2;
        float* bx = g_boxes + (size_t)g * 6;
        bx[0] = p; bx[1] = cx; bx[2] = cy; bx[3] = w; bx[4] = h; bx[5] = (float)am;
        score = p;
    }
    u32 fs = fordf(score);
    g_keys[plane * SS + cell] = ((u64)fs << 32) | (u32)(~(u32)g);
    atomicAdd(&shist[fs >> 21], 1u);
}

// ---------------- kernel 1: decode ------------------------------------------
__global__ void __launch_bounds__(256) k_decode(
    const float* __restrict__ o13, const float* __restrict__ o26,
    const float* __restrict__ o52,
    const float* __restrict__ a13, const float* __restrict__ a26,
    const float* __restrict__ a52,
    const float* __restrict__ c1p, const float* __restrict__ c2p)
{
    __shared__ u32 shist[2048];
    for (int i = threadIdx.x; i < 2048; i += 256) shist[i] = 0;
    if (blockIdx.x == 0 && threadIdx.x == 0) g_cnt = 0;
    __syncthreads();
    int item = blockIdx.x * 256 + threadIdx.x;
    float c1 = *c1p, c2 = *c2p;
    if (item < WTOT) {
        if (item < W52)            decode_v4<52, G52OFF>(item, o52, a52, c1, c2, shist);
        else if (item < W52 + W26) decode_v4<26, G26OFF>(item - W52, o26, a26, c1, c2, shist);
        else                       decode_s13(item - (W52 + W26), o13, a13, c1, c2, shist);
    }
    __syncthreads();
    for (int i = threadIdx.x; i < 2048; i += 256) {
        u32 v = shist[i];
        if (v) atomicAdd(&g_hist1[i], v);
    }
}

// suffix scan of a 2048-bin histogram; find threshold bucket (1024 threads)
__device__ __forceinline__ void suffix_select(u32* sa, u32* sb, const u32* ghist,
                                              u32 target, int* out_b, u32* out_above) {
    int tid = threadIdx.x;
    for (int i = tid; i < 2048; i += BLK) sa[i] = ghist[i];
    __syncthreads();
    u32 *src = sa, *dst = sb;
    for (int off = 1; off < 2048; off <<= 1) {
        for (int i = tid; i < 2048; i += BLK) {
            u32 v = src[i];
            if (i + off < 2048) v += src[i + off];
            dst[i] = v;
        }
        __syncthreads();
        u32* tmp = src; src = dst; dst = tmp;
    }
    for (int i = tid; i < 2048; i += BLK) {
        bool cross = (src[i] >= target) && (i == 2047 || src[i + 1] < target);
        if (cross) {
            *out_b = i;
            if (out_above) *out_above = (i == 2047) ? 0u : src[i + 1];
        }
    }
    __syncthreads();
}

// ---------------- kernel 2: select1 + hist2 ----------------------------------
__global__ void __launch_bounds__(BLK) k_mid()
{
    __shared__ u32 sa[2048], sb[2048];
    __shared__ int s_b1;
    __shared__ u32 s_cA1;
    const int tid = threadIdx.x;
    const int gt = blockIdx.x * BLK + tid;

    suffix_select(sa, sb, g_hist1, (u32)NK, &s_b1, &s_cA1);
    if (blockIdx.x == 0 && tid == 0) { g_b1g = s_b1; g_cA1g = s_cA1; }

    for (int i = tid; i < 2048; i += BLK) sa[i] = 0;
    __syncthreads();
    int B1 = s_b1;
    for (int t = gt; t < NT; t += NTH) {
        u64 k = g_keys[t];
        if ((int)(u32)(k >> 53) == B1)
            atomicAdd(&sa[(u32)(k >> 42) & 2047u], 1u);
    }
    __syncthreads();
    for (int i = tid; i < 2048; i += BLK) {
        u32 v = sa[i];
        if (v) atomicAdd(&g_hist2[i], v);
    }
}

// ---------------- kernel 3: select2 + gather ----------------------------------
__global__ void __launch_bounds__(BLK) k_gather()
{
    __shared__ u32 sa[2048], sb[2048];
    __shared__ int s_b2;
    const int tid = threadIdx.x;
    const int gt = blockIdx.x * BLK + tid;

    int B1 = g_b1g;
    u32 cA1 = g_cA1g;
    suffix_select(sa, sb, g_hist2, (u32)NK - cA1, &s_b2, 0);
    int B2 = s_b2;
    for (int t = gt; t < NT; t += NTH) {
        u64 k = g_keys[t];
        int b1 = (int)(u32)(k >> 53);
        int b2 = (int)((u32)(k >> 42) & 2047u);
        if (b1 > B1 || (b1 == B1 && b2 >= B2)) {
            u32 pos = atomicAdd(&g_cnt, 1u);
            if (pos < (u32)CAP) g_gbuf[pos] = k;
        }
    }
    if (blockIdx.x == 1)
        for (int i = tid; i < 2048; i += BLK) g_hist1[i] = 0;
}

// ---------------- kernel 4: rank-select (single block) ------------------------
__global__ void __launch_bounds__(BLK) k_rank()
{
    __shared__ __align__(16) u64 skeys[CAP];   // 32 KB
    __shared__ u32 s_cnt;
    __shared__ u32 s_maxfs;

    const int tid = threadIdx.x;
    if (tid == 0) { s_cnt = g_cnt; s_maxfs = 0u; }
    for (int i = tid; i < 2048; i += BLK) g_hist2[i] = 0;   // replay reset
    for (int i = tid; i < NK * 6; i += BLK) g_cand[i] = 0.f;
    if (tid < NK) g_alive[tid] = 0;
    __syncthreads();
    u32 cnt = s_cnt; if (cnt > (u32)CAP) cnt = CAP;
    for (u32 i = tid; i < cnt; i += BLK) skeys[i] = g_gbuf[i];
    __syncthreads();

    for (u32 j = tid; j < cnt; j += BLK) {
        u64 kj = skeys[j];
        int r = 0; u32 i = 0;
        for (; i + 4 <= cnt; i += 4)
            r += (int)(skeys[i] > kj) + (int)(skeys[i+1] > kj)
               + (int)(skeys[i+2] > kj) + (int)(skeys[i+3] > kj);
        for (; i < cnt; ++i) r += (int)(skeys[i] > kj);
        u32 fs = (u32)(kj >> 32);
        if (r < NK && fs > 0x80000000u) {
            u32 g = ~(u32)kj;
            const float* bx = g_boxes + (size_t)g * 6;
            float* cd = g_cand + r * 6;
            cd[0] = bx[0]; cd[1] = bx[1]; cd[2] = bx[2];
            cd[3] = bx[3]; cd[4] = bx[4]; cd[5] = bx[5];
            g_alive[r] = 1;
            atomicMax(&s_maxfs, fs);
        }
    }
    __syncthreads();
    if (tid == 0) g_maxp = (s_maxfs > 0x80000000u) ? ifordf(s_maxfs) : 0.f;
}

// ---------------- kernel 5: pairwise suppress bitmask (parallel) --------------
__global__ void __launch_bounds__(512) k_pairs()
{
    int i = blockIdx.x, j = threadIdx.x;
    __shared__ float bi[6];
    if (j < 6) bi[j] = g_cand[i * 6 + j];
    __syncthreads();
    const float* bj = g_cand + j * 6;
    float x1i = bi[1] - bi[3] * 0.5f, y1i = bi[2] - bi[4] * 0.5f;
    float x2i = x1i + bi[3],          y2i = y1i + bi[4];
    float x1j = bj[1] - bj[3] * 0.5f, y1j = bj[2] - bj[4] * 0.5f;
    float x2j = x1j + bj[3],          y2j = y1j + bj[4];
    float iw = fmaxf(fminf(x2i, x2j) - fmaxf(x1i, x1j), 0.f);
    float ih = fmaxf(fminf(y2i, y2j) - fmaxf(y1i, y1j), 0.f);
    float inter = iw * ih;
    float ai = (x2i - x1i) * (y2i - y1i);
    float aj = (x2j - x1j) * (y2j - y1j);
    float iou = inter / (ai + aj - inter);
    bool sup = (bi[5] == bj[5]) || (iou >= 0.5f);
    u32 m = __ballot_sync(0xffffffffu, sup);
    if ((j & 31) == 0) g_sup[i * 16 + (j >> 5)] = m;
}

// ---------------- kernel 6: serial NMS cascade + output -----------------------
__global__ void __launch_bounds__(512) k_nms(float* __restrict__ out, int out_size)
{
    __shared__ __align__(16) unsigned char sm[45056];
    __shared__ u32 s_a0w[16], s_keep[16];
    u32*   ssup  = (u32*)sm;                 // 32 KB
    float* scand = (float*)(sm + 32768);     // 12 KB

    const int tid = threadIdx.x;
    float maxp = g_maxp;
    for (int i = tid; i < NK * 16; i += 512) ssup[i] = g_sup[i];
    for (int i = tid; i < NK * 6;  i += 512) scand[i] = g_cand[i];
    for (int i = NK * 7 + tid; i < out_size; i += 512) out[i] = 0.f;
    {
        bool a0 = (g_alive[tid] != 0) && (scand[tid * 6] > 0.5f * maxp);
        u32 m = __ballot_sync(0xffffffffu, a0);
        if ((tid & 31) == 0) s_a0w[tid >> 5] = m;
    }
    __syncthreads();

    if (tid == 0) {
        u32 sup[16], keep[16];
#pragma unroll
        for (int x = 0; x < 16; ++x) { sup[x] = ~s_a0w[x]; keep[x] = 0u; }
        for (int w = 0; w < 16; ++w) {
            u32 avail = ~sup[w];
            while (avail) {
                int bb = __ffs(avail) - 1;
                int i = (w << 5) + bb;
                keep[w] |= (1u << bb);
#pragma unroll
                for (int x = 0; x < 16; ++x) sup[x] |= ssup[i * 16 + x];
                u32 hi = (bb == 31) ? 0u : (0xffffffffu << (bb + 1));
                avail = ~sup[w] & hi;
            }
        }
#pragma unroll
        for (int x = 0; x < 16; ++x) s_keep[x] = keep[x];
    }
    __syncthreads();

    {
        bool kp = (s_keep[tid >> 5] >> (tid & 31)) & 1u;
        float km = kp ? 1.f : 0.f;
        if (out_size >= NK * 6) {
#pragma unroll
            for (int c = 0; c < 6; ++c) out[tid * 6 + c] = scand[tid * 6 + c] * km;
        }
        if (out_size >= NK * 7) out[NK * 6 + tid] = km;
    }
}

// ---------------- launch: SIX kernels (graph-serialized) ----------------------
extern "C" void kernel_launch(void* const* d_in, const int* in_sizes, int n_in,
                              void* d_out, int out_size) {
    k_decode<<<(WTOT + 255) / 256, 256>>>(
        (const float*)d_in[0], (const float*)d_in[1], (const float*)d_in[2],
        (const float*)d_in[3], (const float*)d_in[4], (const float*)d_in[5],
        (const float*)d_in[6], (const float*)d_in[7]);
    k_mid<<<GRID, BLK>>>();
    k_gather<<<GRID, BLK>>>();
    k_rank<<<1, BLK>>>();
    k_pairs<<<NK, 512>>>();
    k_nms<<<1, 512>>>((float*)d_out, out_size);
}

// round 10
// speedup vs baseline: 2.0396x; 1.0029x over previous
#include <cuda_runtime.h>
#include <cstdint>

typedef unsigned long long u64;
typedef unsigned u32;

#define N13   16224
#define N26   64896
#define N52   259584
#define NT    340704
#define CAP   4096
#define NK    512
#define GRID  148
#define BLK   1024
#define NTH   (GRID*BLK)

#define G26OFF 16224
#define G52OFF 81120

#define W52 64896
#define W26 16224
#define W13 16224
#define WTOT 97344

// ---------------- scratch (static device globals: no allocation) ------------
__device__ u64   g_keys[NT];
__device__ float g_boxes[NT * 6];
__device__ u32   g_hist1[2048];
__device__ u32   g_hist2[2048];
__device__ u32   g_cnt;
__device__ u32   g_maxfs;
__device__ u64   g_gbuf[CAP];
__device__ float g_cand[NK * 6];
__device__ unsigned char g_alive[NK];
__device__ u32   g_sup[NK * 16];
__device__ u32   g_bar_arrive;
__device__ u32   g_bar_gen;

__device__ __forceinline__ u32 fordf(float f) {
    u32 u = __float_as_uint(f);
    return (u & 0x80000000u) ? ~u : (u | 0x80000000u);
}
__device__ __forceinline__ float ifordf(u32 e) {
    return __uint_as_float((e & 0x80000000u) ? (e & 0x7fffffffu) : ~e);
}

// grid barrier: exactly one block per SM (GRID=148, launch_bounds(1024,1))
__device__ __forceinline__ void grid_barrier() {
    __syncthreads();
    __threadfence();
    if (threadIdx.x == 0) {
        volatile u32* vgen = &g_bar_gen;
        u32 gen = *vgen;
        __threadfence();
        u32 a = atomicAdd(&g_bar_arrive, 1u);
        if (a == GRID - 1u) {
            g_bar_arrive = 0u;
            __threadfence();
            atomicAdd(&g_bar_gen, 1u);
        } else {
            while (*vgen == gen) {}
        }
    }
    __threadfence();
    __syncthreads();
}

// ---------------- decode: 4 consecutive cells per thread (vec4, precise) ----
template <int S, int GOFF>
__device__ __forceinline__ void decode_v4(int v,
                                          const float* __restrict__ out,
                                          const float* __restrict__ anc,
                                          float c1, float c2, u32* shist) {
    const int SS = S * S, G4 = SS / 4;
    int plane = v / G4;
    int grp = v - plane * G4;
    int cell0 = grp * 4;
    int b = plane / 3, a = plane - 3 * b;
    const float* pc = out + ((size_t)b * 255 + (size_t)a * 85) * SS + cell0;
    float4 q0 = *(const float4*)pc;
    float4 q1 = *(const float4*)(pc + SS);
    float4 q2 = *(const float4*)(pc + 2 * SS);
    float4 q3 = *(const float4*)(pc + 3 * SS);
    float4 q4 = *(const float4*)(pc + 4 * SS);
    float m0 = -1e30f, m1 = -1e30f, m2 = -1e30f, m3 = -1e30f;
    float s0 = 0.f, s1 = 0.f, s2 = 0.f, s3 = 0.f;
    int i0 = 0, i1 = 0, i2 = 0, i3 = 0;
#pragma unroll 4
    for (int c = 0; c < 80; ++c) {
        float4 l = *(const float4*)(pc + (size_t)(5 + c) * SS);
        s0 += expf(l.x); if (l.x > m0) { m0 = l.x; i0 = c; }
        s1 += expf(l.y); if (l.y > m1) { m1 = l.y; i1 = c; }
        s2 += expf(l.z); if (l.z > m2) { m2 = l.z; i2 = c; }
        s3 += expf(l.w); if (l.w > m3) { m3 = l.w; i3 = c; }
    }
    const float sc = 416.f / (float)S;
    float an0 = anc[2 * a], an1 = anc[2 * a + 1];
    float o0a[4] = {q0.x, q0.y, q0.z, q0.w};
    float o1a[4] = {q1.x, q1.y, q1.z, q1.w};
    float o2a[4] = {q2.x, q2.y, q2.z, q2.w};
    float o3a[4] = {q3.x, q3.y, q3.z, q3.w};
    float o4a[4] = {q4.x, q4.y, q4.z, q4.w};
    float ma[4] = {m0, m1, m2, m3};
    float sa[4] = {s0, s1, s2, s3};
    int   ia[4] = {i0, i1, i2, i3};
#pragma unroll
    for (int k = 0; k < 4; ++k) {
        int cell = cell0 + k;
        int g = GOFF + (b * SS + cell) * 3 + a;
        float score = -1.f;
        if (o0a[k] > 0.f) {
            float obj = 1.f / (1.f + expf(-o0a[k]));
            float p = obj * expf(ma[k]) / sa[k];
            int y = cell / S, x = cell - y * S;
            float cx = ((float)x + o1a[k]) * sc / c1;
            float cy = ((float)y + o2a[k]) * sc / c2;
            float w  = expf(o3a[k]) * an0 / c1;
            float h  = expf(o4a[k]) * an1 / c2;
            float* bx = g_boxes + (size_t)g * 6;
            bx[0] = p; bx[1] = cx; bx[2] = cy; bx[3] = w; bx[4] = h; bx[5] = (float)ia[k];
            score = p;
        }
        u32 fs = fordf(score);
        g_keys[GOFF + plane * SS + cell] = ((u64)fs << 32) | (u32)(~(u32)g);
        atomicAdd(&shist[fs >> 21], 1u);
    }
}

__device__ __forceinline__ void decode_s13(int v,
                                           const float* __restrict__ out,
                                           const float* __restrict__ anc,
                                           float c1, float c2, u32* shist) {
    const int S = 13, SS = 169;
    int plane = v / SS;
    int cell = v - plane * SS;
    int b = plane / 3, a = plane - 3 * b;
    const float* pc = out + ((size_t)b * 255 + (size_t)a * 85) * SS + cell;
    float o0 = pc[0];
    int g = (b * SS + cell) * 3 + a;
    float score = -1.f;
    float m = -1e30f, sum = 0.f; int am = 0;
#pragma unroll 4
    for (int c = 0; c < 80; ++c) {
        float l = pc[(size_t)(5 + c) * SS];
        sum += expf(l);
        if (l > m) { m = l; am = c; }
    }
    if (o0 > 0.f) {
        float obj = 1.f / (1.f + expf(-o0));
        float p = obj * expf(m) / sum;
        int y = cell / S, x = cell - y * S;
        const float sc = 416.f / 13.f;
        float cx = ((float)x + pc[SS]) * sc / c1;
        float cy = ((float)y + pc[2 * SS]) * sc / c2;
        float w  = expf(pc[3 * SS]) * anc[2 * a] / c1;
        float h  = expf(pc[4 * SS]) * anc[2 * a + 1] / c2;
        float* bx = g_boxes + (size_t)g * 6;
        bx[0] = p; bx[1] = cx; bx[2] = cy; bx[3] = w; bx[4] = h; bx[5] = (float)am;
        score = p;
    }
    u32 fs = fordf(score);
    g_keys[plane * SS + cell] = ((u64)fs << 32) | (u32)(~(u32)g);
    atomicAdd(&shist[fs >> 21], 1u);
}

// ---------------- kernel 1: decode + scratch re-init --------------------------
__global__ void __launch_bounds__(256) k_decode(
    const float* __restrict__ o13, const float* __restrict__ o26,
    const float* __restrict__ o52,
    const float* __restrict__ a13, const float* __restrict__ a26,
    const float* __restrict__ a52,
    const float* __restrict__ c1p, const float* __restrict__ c2p)
{
    __shared__ u32 shist[2048];
    for (int i = threadIdx.x; i < 2048; i += 256) shist[i] = 0;
    // replay re-init: all consumed only in k_rest (next graph node)
    if (blockIdx.x == 0 && threadIdx.x == 0) { g_cnt = 0; g_maxfs = 0u; }
    if (blockIdx.x == 2)
        for (int i = threadIdx.x; i < NK * 6; i += 256) g_cand[i] = 0.f;
    if (blockIdx.x == 3 && threadIdx.x < NK) g_alive[threadIdx.x] = 0;
    __syncthreads();
    int item = blockIdx.x * 256 + threadIdx.x;
    float c1 = *c1p, c2 = *c2p;
    if (item < WTOT) {
        if (item < W52)            decode_v4<52, G52OFF>(item, o52, a52, c1, c2, shist);
        else if (item < W52 + W26) decode_v4<26, G26OFF>(item - W52, o26, a26, c1, c2, shist);
        else                       decode_s13(item - (W52 + W26), o13, a13, c1, c2, shist);
    }
    __syncthreads();
    for (int i = threadIdx.x; i < 2048; i += 256) {
        u32 v = shist[i];
        if (v) atomicAdd(&g_hist1[i], v);
    }
}

// suffix scan of a 2048-bin histogram; find threshold bucket (1024 threads)
__device__ __forceinline__ void suffix_select(u32* sa, u32* sb, const u32* ghist,
                                              u32 target, int* out_b, u32* out_above) {
    int tid = threadIdx.x;
    for (int i = tid; i < 2048; i += BLK) sa[i] = ghist[i];
    __syncthreads();
    u32 *src = sa, *dst = sb;
    for (int off = 1; off < 2048; off <<= 1) {
        for (int i = tid; i < 2048; i += BLK) {
            u32 v = src[i];
            if (i + off < 2048) v += src[i + off];
            dst[i] = v;
        }
        __syncthreads();
        u32* tmp = src; src = dst; dst = tmp;
    }
    for (int i = tid; i < 2048; i += BLK) {
        bool cross = (src[i] >= target) && (i == 2047 || src[i + 1] < target);
        if (cross) {
            *out_b = i;
            if (out_above) *out_above = (i == 2047) ? 0u : src[i + 1];
        }
    }
    __syncthreads();
}

// ---------------- kernel 2: everything else (grid 148, spin barriers) --------
__global__ void __launch_bounds__(BLK, 1) k_rest(float* __restrict__ out, int out_size)
{
    __shared__ __align__(16) unsigned char sm[47104];
    __shared__ int s_b1, s_b2;
    __shared__ u32 s_cA1;
    __shared__ u32 s_cnt;
    __shared__ u32 s_a0w[16], s_keep[16];

    const int tid = threadIdx.x;
    const int gt = blockIdx.x * BLK + tid;
    const int lane = tid & 31;

    // ===== P2: select1 + hist2 =====
    {
        u32* sa = (u32*)sm; u32* sb = sa + 2048;
        suffix_select(sa, sb, g_hist1, (u32)NK, &s_b1, &s_cA1);
        for (int i = tid; i < 2048; i += BLK) sa[i] = 0;
        __syncthreads();
        int B1 = s_b1;
        for (int t = gt; t < NT; t += NTH) {
            u64 k = g_keys[t];
            if ((int)(u32)(k >> 53) == B1)
                atomicAdd(&sa[(u32)(k >> 42) & 2047u], 1u);
        }
        __syncthreads();
        for (int i = tid; i < 2048; i += BLK) {
            u32 v = sa[i];
            if (v) atomicAdd(&g_hist2[i], v);
        }
    }
    grid_barrier();

    // ===== P3: select2 + gather =====
    {
        u32* sa = (u32*)sm; u32* sb = sa + 2048;
        suffix_select(sa, sb, g_hist2, (u32)NK - s_cA1, &s_b2, 0);
        int B1 = s_b1, B2 = s_b2;
        for (int t = gt; t < NT; t += NTH) {
            u64 k = g_keys[t];
            int b1 = (int)(u32)(k >> 53);
            int b2 = (int)((u32)(k >> 42) & 2047u);
            if (b1 > B1 || (b1 == B1 && b2 >= B2)) {
                u32 pos = atomicAdd(&g_cnt, 1u);
                if (pos < (u32)CAP) g_gbuf[pos] = k;
            }
        }
    }
    grid_barrier();

    // ===== P4: parallel rank (blocks 0..3) + hist resets (blocks 4,5) =====
    {
        if (tid == 0) s_cnt = g_cnt;
        __syncthreads();
        u32 cnt = s_cnt; if (cnt > (u32)CAP) cnt = CAP;
        if ((u32)(blockIdx.x * BLK) < cnt) {
            u64* skeys = (u64*)sm;                 // 32 KB
            for (u32 i = tid; i < cnt; i += BLK) skeys[i] = g_gbuf[i];
            __syncthreads();
            u32 j = (u32)gt;
            if (j < cnt) {
                u64 kj = skeys[j];
                int r = 0; u32 i = 0;
                for (; i + 4 <= cnt; i += 4)
                    r += (int)(skeys[i] > kj) + (int)(skeys[i+1] > kj)
                       + (int)(skeys[i+2] > kj) + (int)(skeys[i+3] > kj);
                for (; i < cnt; ++i) r += (int)(skeys[i] > kj);
                u32 fs = (u32)(kj >> 32);
                if (r < NK && fs > 0x80000000u) {
                    u32 g = ~(u32)kj;
                    const float* bx = g_boxes + (size_t)g * 6;
                    float* cd = g_cand + r * 6;
                    cd[0] = bx[0]; cd[1] = bx[1]; cd[2] = bx[2];
                    cd[3] = bx[3]; cd[4] = bx[4]; cd[5] = bx[5];
                    g_alive[r] = 1;
                    atomicMax(&g_maxfs, fs);
                }
            }
        }
        if (blockIdx.x == 4)
            for (int i = tid; i < 2048; i += BLK) g_hist1[i] = 0;
        if (blockIdx.x == 5)
            for (int i = tid; i < 2048; i += BLK) g_hist2[i] = 0;
    }
    grid_barrier();

    // ===== P5: parallel pairwise suppress bitmask =====
    {
        __shared__ float bi[2][6];
        int half = tid >> 9;                  // 0 or 1: two rows per iteration
        int col  = tid & 511;
        for (int row0 = blockIdx.x * 2; row0 < NK; row0 += GRID * 2) {
            int row = row0 + half;
            if (tid < 12) bi[tid / 6][tid % 6] = g_cand[(row0 + tid / 6) * 6 + tid % 6];
            __syncthreads();
            {
                const float* bI = bi[half];
                const float* bj = g_cand + col * 6;
                float x1i = bI[1] - bI[3] * 0.5f, y1i = bI[2] - bI[4] * 0.5f;
                float x2i = x1i + bI[3],          y2i = y1i + bI[4];
                float x1j = bj[1] - bj[3] * 0.5f, y1j = bj[2] - bj[4] * 0.5f;
                float x2j = x1j + bj[3],          y2j = y1j + bj[4];
                float iw = fmaxf(fminf(x2i, x2j) - fmaxf(x1i, x1j), 0.f);
                float ih = fmaxf(fminf(y2i, y2j) - fmaxf(y1i, y1j), 0.f);
                float inter = iw * ih;
                float ai = (x2i - x1i) * (y2i - y1i);
                float aj = (x2j - x1j) * (y2j - y1j);
                float iou = inter / (ai + aj - inter);
                bool sup = (bI[5] == bj[5]) || (iou >= 0.5f);
                u32 m = __ballot_sync(0xffffffffu, sup);
                if (lane == 0) g_sup[row * 16 + (col >> 5)] = m;
            }
            __syncthreads();
        }
    }
    grid_barrier();   // last barrier

    // tail-fill of out beyond 512*7 (all blocks; disjoint from block-0 writes)
    for (int i = NK * 7 + gt; i < out_size; i += NTH) out[i] = 0.f;
    if (blockIdx.x != 0) return;

    // ===== P6 (block 0): alive0 + serial cascade + output =====
    {
        u32*   ssup  = (u32*)sm;                 // 32 KB
        float* scand = (float*)(sm + 32768);     // 12 KB
        float maxp = (g_maxfs > 0x80000000u) ? ifordf(g_maxfs) : 0.f;
        for (int i = tid; i < NK * 16; i += BLK) ssup[i] = g_sup[i];
        for (int i = tid; i < NK * 6;  i += BLK) scand[i] = g_cand[i];
        if (tid < NK) {
            bool a0 = (g_alive[tid] != 0) && (scand[tid * 6] > 0.5f * maxp);
            u32 m = __ballot_sync(0xffffffffu, a0);
            if (lane == 0) s_a0w[tid >> 5] = m;
        }
        __syncthreads();

        if (tid == 0) {
            u32 sup[16], keep[16];
#pragma unroll
            for (int x = 0; x < 16; ++x) { sup[x] = ~s_a0w[x]; keep[x] = 0u; }
            for (int w = 0; w < 16; ++w) {
                u32 avail = ~sup[w];
                while (avail) {
                    int bb = __ffs(avail) - 1;
                    int i = (w << 5) + bb;
                    keep[w] |= (1u << bb);
#pragma unroll
                    for (int x = 0; x < 16; ++x) sup[x] |= ssup[i * 16 + x];
                    u32 hi = (bb == 31) ? 0u : (0xffffffffu << (bb + 1));
                    avail = ~sup[w] & hi;
                }
            }
#pragma unroll
            for (int x = 0; x < 16; ++x) s_keep[x] = keep[x];
        }
        __syncthreads();

        if (tid < NK) {
            bool kp = (s_keep[tid >> 5] >> (tid & 31)) & 1u;
            float km = kp ? 1.f : 0.f;
            if (out_size >= NK * 6) {
#pragma unroll
                for (int c = 0; c < 6; ++c) out[tid * 6 + c] = scand[tid * 6 + c] * km;
            }
            if (out_size >= NK * 7) out[NK * 6 + tid] = km;
        }
    }
}

// ---------------- launch: TWO kernels ------------------------------------------
extern "C" void kernel_launch(void* const* d_in, const int* in_sizes, int n_in,
                              void* d_out, int out_size) {
    k_decode<<<(WTOT + 255) / 256, 256>>>(
        (const float*)d_in[0], (const float*)d_in[1], (const float*)d_in[2],
        (const float*)d_in[3], (const float*)d_in[4], (const float*)d_in[5],
        (const float*)d_in[6], (const float*)d_in[7]);
    k_rest<<<GRID, BLK>>>((float*)d_out, out_size);
}

// round 11
// speedup vs baseline: 2.4380x; 1.1953x over previous
#include <cuda_runtime.h>
#include <cstdint>

typedef unsigned long long u64;
typedef unsigned u32;

#define N13   16224
#define N26   64896
#define N52   259584
#define NT    340704
#define CAP   4096
#define NK    512
#define HB    4096            // score histogram bins: (fs>>18)-8192 for fs in (0x80000000, 0xBF800000)
#define GRID  148
#define BLK   1024
#define NTH   (GRID*BLK)

#define G26OFF 16224
#define G52OFF 81120

#define W52 64896
#define W26 16224
#define W13 16224
#define WTOT 97344

// ---------------- scratch (static device globals: no allocation) ------------
__device__ u64   g_keys[NT];
__device__ float g_boxes[NT * 6];
__device__ u32   g_hist[HB];
__device__ u32   g_cnt;
__device__ u32   g_maxfs;
__device__ u64   g_gbuf[CAP];
__device__ float g_cand[NK * 6];
__device__ unsigned char g_alive[NK];
__device__ u32   g_sup[NK * 16];
__device__ u32   g_bar_arrive;
__device__ u32   g_bar_gen;

__device__ __forceinline__ u32 fordf(float f) {
    u32 u = __float_as_uint(f);
    return (u & 0x80000000u) ? ~u : (u | 0x80000000u);
}
__device__ __forceinline__ float ifordf(u32 e) {
    return __uint_as_float((e & 0x80000000u) ? (e & 0x7fffffffu) : ~e);
}

// grid barrier: exactly one block per SM (GRID=148, launch_bounds(1024,1))
__device__ __forceinline__ void grid_barrier() {
    __syncthreads();
    __threadfence();
    if (threadIdx.x == 0) {
        volatile u32* vgen = &g_bar_gen;
        u32 gen = *vgen;
        __threadfence();
        u32 a = atomicAdd(&g_bar_arrive, 1u);
        if (a == GRID - 1u) {
            g_bar_arrive = 0u;
            __threadfence();
            atomicAdd(&g_bar_gen, 1u);
        } else {
            while (*vgen == gen) {}
        }
    }
    __threadfence();
    __syncthreads();
}

// ---------------- decode: 4 consecutive cells per thread (vec4, precise) ----
template <int S, int GOFF>
__device__ __forceinline__ void decode_v4(int v,
                                          const float* __restrict__ out,
                                          const float* __restrict__ anc,
                                          float c1, float c2, u32* shist) {
    const int SS = S * S, G4 = SS / 4;
    int plane = v / G4;
    int grp = v - plane * G4;
    int cell0 = grp * 4;
    int b = plane / 3, a = plane - 3 * b;
    const float* pc = out + ((size_t)b * 255 + (size_t)a * 85) * SS + cell0;
    float4 q0 = *(const float4*)pc;
    float4 q1 = *(const float4*)(pc + SS);
    float4 q2 = *(const float4*)(pc + 2 * SS);
    float4 q3 = *(const float4*)(pc + 3 * SS);
    float4 q4 = *(const float4*)(pc + 4 * SS);
    float m0 = -1e30f, m1 = -1e30f, m2 = -1e30f, m3 = -1e30f;
    float s0 = 0.f, s1 = 0.f, s2 = 0.f, s3 = 0.f;
    int i0 = 0, i1 = 0, i2 = 0, i3 = 0;
#pragma unroll 4
    for (int c = 0; c < 80; ++c) {
        float4 l = *(const float4*)(pc + (size_t)(5 + c) * SS);
        s0 += expf(l.x); if (l.x > m0) { m0 = l.x; i0 = c; }
        s1 += expf(l.y); if (l.y > m1) { m1 = l.y; i1 = c; }
        s2 += expf(l.z); if (l.z > m2) { m2 = l.z; i2 = c; }
        s3 += expf(l.w); if (l.w > m3) { m3 = l.w; i3 = c; }
    }
    const float sc = 416.f / (float)S;
    float an0 = anc[2 * a], an1 = anc[2 * a + 1];
    float o0a[4] = {q0.x, q0.y, q0.z, q0.w};
    float o1a[4] = {q1.x, q1.y, q1.z, q1.w};
    float o2a[4] = {q2.x, q2.y, q2.z, q2.w};
    float o3a[4] = {q3.x, q3.y, q3.z, q3.w};
    float o4a[4] = {q4.x, q4.y, q4.z, q4.w};
    float ma[4] = {m0, m1, m2, m3};
    float sa[4] = {s0, s1, s2, s3};
    int   ia[4] = {i0, i1, i2, i3};
#pragma unroll
    for (int k = 0; k < 4; ++k) {
        int cell = cell0 + k;
        int g = GOFF + (b * SS + cell) * 3 + a;
        float score = -1.f;
        if (o0a[k] > 0.f) {
            float obj = 1.f / (1.f + expf(-o0a[k]));
            float p = obj * expf(ma[k]) / sa[k];
            int y = cell / S, x = cell - y * S;
            float cx = ((float)x + o1a[k]) * sc / c1;
            float cy = ((float)y + o2a[k]) * sc / c2;
            float w  = expf(o3a[k]) * an0 / c1;
            float h  = expf(o4a[k]) * an1 / c2;
            float* bx = g_boxes + (size_t)g * 6;
            bx[0] = p; bx[1] = cx; bx[2] = cy; bx[3] = w; bx[4] = h; bx[5] = (float)ia[k];
            score = p;
        }
        u32 fs = fordf(score);
        g_keys[GOFF + plane * SS + cell] = ((u64)fs << 32) | (u32)(~(u32)g);
        if (fs > 0x80000000u) atomicAdd(&shist[(fs >> 18) - 8192u], 1u);
    }
}

__device__ __forceinline__ void decode_s13(int v,
                                           const float* __restrict__ out,
                                           const float* __restrict__ anc,
                                           float c1, float c2, u32* shist) {
    const int S = 13, SS = 169;
    int plane = v / SS;
    int cell = v - plane * SS;
    int b = plane / 3, a = plane - 3 * b;
    const float* pc = out + ((size_t)b * 255 + (size_t)a * 85) * SS + cell;
    float o0 = pc[0];
    int g = (b * SS + cell) * 3 + a;
    float score = -1.f;
    float m = -1e30f, sum = 0.f; int am = 0;
#pragma unroll 4
    for (int c = 0; c < 80; ++c) {
        float l = pc[(size_t)(5 + c) * SS];
        sum += expf(l);
        if (l > m) { m = l; am = c; }
    }
    if (o0 > 0.f) {
        float obj = 1.f / (1.f + expf(-o0));
        float p = obj * expf(m) / sum;
        int y = cell / S, x = cell - y * S;
        const float sc = 416.f / 13.f;
        float cx = ((float)x + pc[SS]) * sc / c1;
        float cy = ((float)y + pc[2 * SS]) * sc / c2;
        float w  = expf(pc[3 * SS]) * anc[2 * a] / c1;
        float h  = expf(pc[4 * SS]) * anc[2 * a + 1] / c2;
        float* bx = g_boxes + (size_t)g * 6;
        bx[0] = p; bx[1] = cx; bx[2] = cy; bx[3] = w; bx[4] = h; bx[5] = (float)am;
        score = p;
    }
    u32 fs = fordf(score);
    g_keys[plane * SS + cell] = ((u64)fs << 32) | (u32)(~(u32)g);
    if (fs > 0x80000000u) atomicAdd(&shist[(fs >> 18) - 8192u], 1u);
}

// ---------------- kernel 1: decode + scratch re-init --------------------------
__global__ void __launch_bounds__(256) k_decode(
    const float* __restrict__ o13, const float* __restrict__ o26,
    const float* __restrict__ o52,
    const float* __restrict__ a13, const float* __restrict__ a26,
    const float* __restrict__ a52,
    const float* __restrict__ c1p, const float* __restrict__ c2p)
{
    __shared__ u32 shist[HB];
    for (int i = threadIdx.x; i < HB; i += 256) shist[i] = 0;
    // replay re-init (all consumed only in k_rest, the next graph node)
    if (blockIdx.x == 0 && threadIdx.x == 0) { g_cnt = 0; g_maxfs = 0u; }
    if (blockIdx.x == 2)
        for (int i = threadIdx.x; i < NK * 6; i += 256) g_cand[i] = 0.f;
    if (blockIdx.x == 3 && threadIdx.x < NK) g_alive[threadIdx.x] = 0;
    __syncthreads();
    int item = blockIdx.x * 256 + threadIdx.x;
    float c1 = *c1p, c2 = *c2p;
    if (item < WTOT) {
        if (item < W52)            decode_v4<52, G52OFF>(item, o52, a52, c1, c2, shist);
        else if (item < W52 + W26) decode_v4<26, G26OFF>(item - W52, o26, a26, c1, c2, shist);
        else                       decode_s13(item - (W52 + W26), o13, a13, c1, c2, shist);
    }
    __syncthreads();
    for (int i = threadIdx.x; i < HB; i += 256) {
        u32 v = shist[i];
        if (v) atomicAdd(&g_hist[i], v);
    }
}

// ---------------- kernel 2: select + gather + rank + pairs + NMS -------------
__global__ void __launch_bounds__(BLK, 1) k_rest(float* __restrict__ out, int out_size)
{
    __shared__ __align__(16) unsigned char sm[47104];
    __shared__ int s_B;
    __shared__ u32 s_cnt;
    __shared__ u32 s_a0w[16], s_keep[16];

    const int tid = threadIdx.x;
    const int gt = blockIdx.x * BLK + tid;
    const int lane = tid & 31;
    const int wid = tid >> 5;

    // ===== P1: single-level select (every block, redundant) + gather =====
    {
        u32* sa = (u32*)sm;            // 1024 partials
        u32* sb = sa + 1024;
        if (tid == 0) s_B = 0;         // default: gather all positives (<512 total)
        uint4 mybins = ((const uint4*)g_hist)[tid];          // bins [4t, 4t+4)
        sa[tid] = mybins.x + mybins.y + mybins.z + mybins.w;
        __syncthreads();
        u32 *src = sa, *dst = sb;
        for (int off = 1; off < 1024; off <<= 1) {
            u32 v = src[tid];
            if (tid + off < 1024) v += src[tid + off];
            dst[tid] = v;
            __syncthreads();
            u32* tmp = src; src = dst; dst = tmp;
        }
        u32 run = (tid < 1023) ? src[tid + 1] : 0u;          // suffix after my bins
        u32 prev;
        prev = run; run += mybins.w; if (prev < NK && run >= NK) s_B = 4 * tid + 3;
        prev = run; run += mybins.z; if (prev < NK && run >= NK) s_B = 4 * tid + 2;
        prev = run; run += mybins.y; if (prev < NK && run >= NK) s_B = 4 * tid + 1;
        prev = run; run += mybins.x; if (prev < NK && run >= NK) s_B = 4 * tid + 0;
        __syncthreads();
        u32 B = (u32)s_B;
        for (int t = gt; t < NT; t += NTH) {
            u64 k = g_keys[t];
            u32 fs = (u32)(k >> 32);
            if (fs > 0x80000000u && ((fs >> 18) - 8192u) >= B) {
                u32 pos = atomicAdd(&g_cnt, 1u);
                if (pos < (u32)CAP) g_gbuf[pos] = k;
            }
        }
    }
    grid_barrier();

    // ===== P2: warp-per-candidate rank + hist reset =====
    {
        if (tid == 0) s_cnt = g_cnt;
        __syncthreads();
        u32 cnt = s_cnt; if (cnt > (u32)CAP) cnt = CAP;
        if ((u32)(blockIdx.x * 32) < cnt) {                   // this block has warps with work
            u64* skeys = (u64*)sm;                            // 32 KB
            for (u32 i = tid; i < cnt; i += BLK) skeys[i] = g_gbuf[i];
            __syncthreads();
            u32 j = (u32)(blockIdx.x * 32 + wid);
            if (j < cnt) {
                u64 kj = skeys[j];
                int r = 0;
                for (u32 i = lane; i < cnt; i += 32) r += (int)(skeys[i] > kj);
#pragma unroll
                for (int o = 16; o > 0; o >>= 1) r += __shfl_xor_sync(0xffffffffu, r, o);
                u32 fs = (u32)(kj >> 32);
                if (r < NK) {                                 // all gathered are positive
                    u32 g = ~(u32)kj;
                    const float* bx = g_boxes + (size_t)g * 6;
                    if (lane < 6) g_cand[r * 6 + lane] = bx[lane];
                    if (lane == 0) {
                        g_alive[r] = 1;
                        atomicMax(&g_maxfs, fs);
                    }
                }
            }
        }
        if (blockIdx.x == GRID - 1)                           // never ranks (base 4704 >= CAP)
            for (int i = tid; i < HB; i += BLK) g_hist[i] = 0;
    }
    grid_barrier();

    // ===== P3: parallel pairwise suppress bitmask =====
    {
        __shared__ float bi[2][6];
        int half = tid >> 9;
        int col  = tid & 511;
        for (int row0 = blockIdx.x * 2; row0 < NK; row0 += GRID * 2) {
            int row = row0 + half;
            if (tid < 12) bi[tid / 6][tid % 6] = g_cand[(row0 + tid / 6) * 6 + tid % 6];
            __syncthreads();
            {
                const float* bI = bi[half];
                const float* bj = g_cand + col * 6;
                float x1i = bI[1] - bI[3] * 0.5f, y1i = bI[2] - bI[4] * 0.5f;
                float x2i = x1i + bI[3],          y2i = y1i + bI[4];
                float x1j = bj[1] - bj[3] * 0.5f, y1j = bj[2] - bj[4] * 0.5f;
                float x2j = x1j + bj[3],          y2j = y1j + bj[4];
                float iw = fmaxf(fminf(x2i, x2j) - fmaxf(x1i, x1j), 0.f);
                float ih = fmaxf(fminf(y2i, y2j) - fmaxf(y1i, y1j), 0.f);
                float inter = iw * ih;
                float ai = (x2i - x1i) * (y2i - y1i);
                float aj = (x2j - x1j) * (y2j - y1j);
                float iou = inter / (ai + aj - inter);
                bool sup = (bI[5] == bj[5]) || (iou >= 0.5f);
                u32 m = __ballot_sync(0xffffffffu, sup);
                if (lane == 0) g_sup[row * 16 + (col >> 5)] = m;
            }
            __syncthreads();
        }
    }
    grid_barrier();   // last barrier

    // tail-fill of out beyond 512*7 (all blocks; disjoint from block-0 writes)
    for (int i = NK * 7 + gt; i < out_size; i += NTH) out[i] = 0.f;
    if (blockIdx.x != 0) return;

    // ===== P4 (block 0): alive0 + serial cascade + output =====
    {
        u32*   ssup  = (u32*)sm;                 // 32 KB
        float* scand = (float*)(sm + 32768);     // 12 KB
        float maxp = (g_maxfs > 0x80000000u) ? ifordf(g_maxfs) : 0.f;
        for (int i = tid; i < NK * 16; i += BLK) ssup[i] = g_sup[i];
        for (int i = tid; i < NK * 6;  i += BLK) scand[i] = g_cand[i];
        if (tid < NK) {
            bool a0 = (g_alive[tid] != 0) && (scand[tid * 6] > 0.5f * maxp);
            u32 m = __ballot_sync(0xffffffffu, a0);
            if (lane == 0) s_a0w[tid >> 5] = m;
        }
        __syncthreads();

        if (tid == 0) {
            u32 sup[16], keep[16];
#pragma unroll
            for (int x = 0; x < 16; ++x) { sup[x] = ~s_a0w[x]; keep[x] = 0u; }
            for (int w = 0; w < 16; ++w) {
                u32 avail = ~sup[w];
                while (avail) {
                    int bb = __ffs(avail) - 1;
                    int i = (w << 5) + bb;
                    keep[w] |= (1u << bb);
#pragma unroll
                    for (int x = 0; x < 16; ++x) sup[x] |= ssup[i * 16 + x];
                    u32 hi = (bb == 31) ? 0u : (0xffffffffu << (bb + 1));
                    avail = ~sup[w] & hi;
                }
            }
#pragma unroll
            for (int x = 0; x < 16; ++x) s_keep[x] = keep[x];
        }
        __syncthreads();

        if (tid < NK) {
            bool kp = (s_keep[tid >> 5] >> (tid & 31)) & 1u;
            float km = kp ? 1.f : 0.f;
            if (out_size >= NK * 6) {
#pragma unroll
                for (int c = 0; c < 6; ++c) out[tid * 6 + c] = scand[tid * 6 + c] * km;
            }
            if (out_size >= NK * 7) out[NK * 6 + tid] = km;
        }
    }
}

// ---------------- launch: TWO kernels ------------------------------------------
extern "C" void kernel_launch(void* const* d_in, const int* in_sizes, int n_in,
                              void* d_out, int out_size) {
    k_decode<<<(WTOT + 255) / 256, 256>>>(
        (const float*)d_in[0], (const float*)d_in[1], (const float*)d_in[2],
        (const float*)d_in[3], (const float*)d_in[4], (const float*)d_in[5],
        (const float*)d_in[6], (const float*)d_in[7]);
    k_rest<<<GRID, BLK>>>((float*)d_out, out_size);
}